// round 1
// baseline (speedup 1.0000x reference)
#include <cuda_runtime.h>
#include <math.h>

#define D_MODEL 512
#define NBATCH  2
#define SEQ     4096
#define NHEADS  8
#define HDIM    64
#define MROWS   (NBATCH * SEQ)   // 8192

// Scratch: projected Q, K, V and attention output (pre output-projection).
__device__ float g_Q[MROWS * D_MODEL];
__device__ float g_K[MROWS * D_MODEL];
__device__ float g_V[MROWS * D_MODEL];
__device__ float g_AO[MROWS * D_MODEL];

// ---------------------------------------------------------------------------
// C[m,n] = sum_k A[m,k] * B[n,k] + bias[n]      (torch Linear: x @ W^T + b)
// A: [M, 512] row-major, B: [512, 512] row-major. Tile 64x64, BK=16,
// 256 threads, each computes a 4x4 micro-tile (rows ty+16i, cols tx+16j).
// ---------------------------------------------------------------------------
__global__ void gemm_abT_bias(const float* __restrict__ A,
                              const float* __restrict__ B,
                              const float* __restrict__ bias,
                              float* __restrict__ C, int M) {
    __shared__ float As[64][17];
    __shared__ float Bs[64][17];

    const int tx = threadIdx.x & 15;
    const int ty = threadIdx.x >> 4;
    const int bm = blockIdx.x * 64;
    const int bn = blockIdx.y * 64;

    float acc[4][4] = {};

    const int lr = threadIdx.x >> 2;         // 0..63
    const int lc = (threadIdx.x & 3) * 4;    // 0,4,8,12

    for (int k0 = 0; k0 < D_MODEL; k0 += 16) {
        float4 a4 = *(const float4*)&A[(size_t)(bm + lr) * D_MODEL + k0 + lc];
        As[lr][lc + 0] = a4.x; As[lr][lc + 1] = a4.y;
        As[lr][lc + 2] = a4.z; As[lr][lc + 3] = a4.w;
        float4 b4 = *(const float4*)&B[(size_t)(bn + lr) * D_MODEL + k0 + lc];
        Bs[lr][lc + 0] = b4.x; Bs[lr][lc + 1] = b4.y;
        Bs[lr][lc + 2] = b4.z; Bs[lr][lc + 3] = b4.w;
        __syncthreads();

        #pragma unroll
        for (int kk = 0; kk < 16; kk++) {
            float a[4], b[4];
            #pragma unroll
            for (int i = 0; i < 4; i++) a[i] = As[ty + 16 * i][kk];
            #pragma unroll
            for (int j = 0; j < 4; j++) b[j] = Bs[tx + 16 * j][kk];
            #pragma unroll
            for (int i = 0; i < 4; i++)
                #pragma unroll
                for (int j = 0; j < 4; j++)
                    acc[i][j] = fmaf(a[i], b[j], acc[i][j]);
        }
        __syncthreads();
    }

    #pragma unroll
    for (int j = 0; j < 4; j++) {
        float bb = bias[bn + tx + 16 * j];
        #pragma unroll
        for (int i = 0; i < 4; i++)
            C[(size_t)(bm + ty + 16 * i) * D_MODEL + bn + tx + 16 * j] = acc[i][j] + bb;
    }
}

// ---------------------------------------------------------------------------
// Flash attention, fp32, online softmax.
// Grid: (SEQ/64, NHEADS, NBATCH). Block: 256 threads.
// Each block: 64 query rows x Hd=64 output, loop over 64-row KV chunks.
// smem: Qs[64][65], KVs[64][65] (K then reused for V), Ss[64][65], m/l/resc[64].
// ---------------------------------------------------------------------------
__global__ void flash_attn(const float* __restrict__ Q,
                           const float* __restrict__ K,
                           const float* __restrict__ V,
                           float* __restrict__ O) {
    extern __shared__ float sm[];
    float* Qs   = sm;                 // 64*65
    float* KVs  = Qs + 64 * 65;       // 64*65
    float* Ss   = KVs + 64 * 65;      // 64*65
    float* mrow = Ss + 64 * 65;       // 64
    float* lrow = mrow + 64;          // 64
    float* resc = lrow + 64;          // 64

    const int tx = threadIdx.x & 15;
    const int ty = threadIdx.x >> 4;
    const int qblk = blockIdx.x;
    const int h    = blockIdx.y;
    const int n    = blockIdx.z;
    const float scale = 0.125f;       // 1/sqrt(64)

    const int rowbase = n * SEQ + qblk * 64;
    const int col0    = h * HDIM;

    // Load Q tile [64][64]
    for (int i = threadIdx.x; i < 64 * 64; i += 256) {
        int r = i >> 6, c = i & 63;
        Qs[r * 65 + c] = Q[(size_t)(rowbase + r) * D_MODEL + col0 + c];
    }
    if (threadIdx.x < 64) { mrow[threadIdx.x] = -1e30f; lrow[threadIdx.x] = 0.0f; }

    float acc[4][4] = {};
    __syncthreads();

    for (int s0 = 0; s0 < SEQ; s0 += 64) {
        // Load K chunk
        for (int i = threadIdx.x; i < 64 * 64; i += 256) {
            int r = i >> 6, c = i & 63;
            KVs[r * 65 + c] = K[(size_t)(n * SEQ + s0 + r) * D_MODEL + col0 + c];
        }
        __syncthreads();

        // Scores: S[r][c] = scale * Q[r] . K[c]
        #pragma unroll
        for (int i = 0; i < 4; i++) {
            #pragma unroll
            for (int j = 0; j < 4; j++) {
                int r = ty + 16 * i, c = tx + 16 * j;
                float s = 0.0f;
                #pragma unroll
                for (int k = 0; k < 64; k++)
                    s = fmaf(Qs[r * 65 + k], KVs[c * 65 + k], s);
                Ss[r * 65 + c] = s * scale;
            }
        }
        __syncthreads();

        // Online softmax per row (one thread per row)
        if (threadIdx.x < 64) {
            int r = threadIdx.x;
            float mold = mrow[r];
            float mx = mold;
            #pragma unroll 8
            for (int c = 0; c < 64; c++) mx = fmaxf(mx, Ss[r * 65 + c]);
            float corr = __expf(mold - mx);
            float l = lrow[r] * corr;
            #pragma unroll 8
            for (int c = 0; c < 64; c++) {
                float p = __expf(Ss[r * 65 + c] - mx);
                Ss[r * 65 + c] = p;
                l += p;
            }
            mrow[r] = mx; lrow[r] = l; resc[r] = corr;
        }

        // Load V chunk (overwrites KVs; K already consumed, sync'd above)
        for (int i = threadIdx.x; i < 64 * 64; i += 256) {
            int r = i >> 6, c = i & 63;
            KVs[r * 65 + c] = V[(size_t)(n * SEQ + s0 + r) * D_MODEL + col0 + c];
        }
        __syncthreads();

        // Rescale accumulators, then O += P @ V
        #pragma unroll
        for (int i = 0; i < 4; i++) {
            float corr = resc[ty + 16 * i];
            #pragma unroll
            for (int j = 0; j < 4; j++) acc[i][j] *= corr;
        }
        #pragma unroll
        for (int k = 0; k < 64; k++) {
            float p[4], v[4];
            #pragma unroll
            for (int i = 0; i < 4; i++) p[i] = Ss[(ty + 16 * i) * 65 + k];
            #pragma unroll
            for (int j = 0; j < 4; j++) v[j] = KVs[k * 65 + tx + 16 * j];
            #pragma unroll
            for (int i = 0; i < 4; i++)
                #pragma unroll
                for (int j = 0; j < 4; j++)
                    acc[i][j] = fmaf(p[i], v[j], acc[i][j]);
        }
        __syncthreads();   // before next chunk overwrites KVs / Ss
    }

    // Normalize and store
    #pragma unroll
    for (int i = 0; i < 4; i++) {
        float inv_l = 1.0f / lrow[ty + 16 * i];
        #pragma unroll
        for (int j = 0; j < 4; j++)
            O[(size_t)(rowbase + ty + 16 * i) * D_MODEL + col0 + tx + 16 * j] =
                acc[i][j] * inv_l;
    }
}

// ---------------------------------------------------------------------------

extern "C" void kernel_launch(void* const* d_in, const int* in_sizes, int n_in,
                              void* d_out, int out_size) {
    const float* query = (const float*)d_in[0];
    const float* key   = (const float*)d_in[1];
    const float* value = (const float*)d_in[2];
    const float* Wq    = (const float*)d_in[3];
    const float* bq    = (const float*)d_in[4];
    const float* Wk    = (const float*)d_in[5];
    const float* bk    = (const float*)d_in[6];
    const float* Wv    = (const float*)d_in[7];
    const float* bv    = (const float*)d_in[8];
    const float* Wo    = (const float*)d_in[9];
    const float* bo    = (const float*)d_in[10];
    float* out = (float*)d_out;

    float *qp, *kp, *vp, *ao;
    cudaGetSymbolAddress((void**)&qp, g_Q);
    cudaGetSymbolAddress((void**)&kp, g_K);
    cudaGetSymbolAddress((void**)&vp, g_V);
    cudaGetSymbolAddress((void**)&ao, g_AO);

    dim3 gemm_grid(MROWS / 64, D_MODEL / 64);
    dim3 gemm_blk(256);

    gemm_abT_bias<<<gemm_grid, gemm_blk>>>(query, Wq, bq, qp, MROWS);
    gemm_abT_bias<<<gemm_grid, gemm_blk>>>(key,   Wk, bk, kp, MROWS);
    gemm_abT_bias<<<gemm_grid, gemm_blk>>>(value, Wv, bv, vp, MROWS);

    size_t flash_smem = (3 * 64 * 65 + 3 * 64) * sizeof(float);  // ~50.7 KB
    cudaFuncSetAttribute(flash_attn, cudaFuncAttributeMaxDynamicSharedMemorySize,
                         (int)flash_smem);
    dim3 flash_grid(SEQ / 64, NHEADS, NBATCH);
    flash_attn<<<flash_grid, 256, flash_smem>>>(qp, kp, vp, ao);

    gemm_abT_bias<<<gemm_grid, gemm_blk>>>(ao, Wo, bo, out, MROWS);
}

// round 2
// speedup vs baseline: 4.1649x; 4.1649x over previous
#include <cuda_runtime.h>
#include <math.h>
#include <stdint.h>

#define D_MODEL 512
#define NBATCH  2
#define SEQ     4096
#define NHEADS  8
#define HDIM    64
#define MROWS   (NBATCH * SEQ)   // 8192
#define LDW     68               // smem row stride (64 + 4 pad -> conflict-free frags)

// Scratch: projected Q, K, V and attention output (pre output-projection).
__device__ float g_Q[MROWS * D_MODEL];
__device__ float g_K[MROWS * D_MODEL];
__device__ float g_V[MROWS * D_MODEL];
__device__ float g_AO[MROWS * D_MODEL];

// ---------------------------------------------------------------------------
// fp32 -> tf32 (round to nearest) kept in a b32 register
// ---------------------------------------------------------------------------
__device__ __forceinline__ uint32_t f2tf32(float f) {
    uint32_t u;
    asm("cvt.rna.tf32.f32 %0, %1;" : "=r"(u) : "f"(f));
    return u;
}

__device__ __forceinline__ void mma_tf32(float c[4],
                                         uint32_t a0, uint32_t a1, uint32_t a2, uint32_t a3,
                                         uint32_t b0, uint32_t b1) {
    asm volatile(
        "mma.sync.aligned.m16n8k8.row.col.f32.tf32.tf32.f32 "
        "{%0,%1,%2,%3}, {%4,%5,%6,%7}, {%8,%9}, {%0,%1,%2,%3};\n"
        : "+f"(c[0]), "+f"(c[1]), "+f"(c[2]), "+f"(c[3])
        : "r"(a0), "r"(a1), "r"(a2), "r"(a3), "r"(b0), "r"(b1));
}

// ---------------------------------------------------------------------------
// C[m,n] = sum_k A[m,k] * B[n,k] + bias[n]   (fp32, unchanged from R0)
// ---------------------------------------------------------------------------
__global__ void gemm_abT_bias(const float* __restrict__ A,
                              const float* __restrict__ B,
                              const float* __restrict__ bias,
                              float* __restrict__ C, int M) {
    __shared__ float As[64][17];
    __shared__ float Bs[64][17];

    const int tx = threadIdx.x & 15;
    const int ty = threadIdx.x >> 4;
    const int bm = blockIdx.x * 64;
    const int bn = blockIdx.y * 64;

    float acc[4][4] = {};

    const int lr = threadIdx.x >> 2;
    const int lc = (threadIdx.x & 3) * 4;

    for (int k0 = 0; k0 < D_MODEL; k0 += 16) {
        float4 a4 = *(const float4*)&A[(size_t)(bm + lr) * D_MODEL + k0 + lc];
        As[lr][lc + 0] = a4.x; As[lr][lc + 1] = a4.y;
        As[lr][lc + 2] = a4.z; As[lr][lc + 3] = a4.w;
        float4 b4 = *(const float4*)&B[(size_t)(bn + lr) * D_MODEL + k0 + lc];
        Bs[lr][lc + 0] = b4.x; Bs[lr][lc + 1] = b4.y;
        Bs[lr][lc + 2] = b4.z; Bs[lr][lc + 3] = b4.w;
        __syncthreads();

        #pragma unroll
        for (int kk = 0; kk < 16; kk++) {
            float a[4], b[4];
            #pragma unroll
            for (int i = 0; i < 4; i++) a[i] = As[ty + 16 * i][kk];
            #pragma unroll
            for (int j = 0; j < 4; j++) b[j] = Bs[tx + 16 * j][kk];
            #pragma unroll
            for (int i = 0; i < 4; i++)
                #pragma unroll
                for (int j = 0; j < 4; j++)
                    acc[i][j] = fmaf(a[i], b[j], acc[i][j]);
        }
        __syncthreads();
    }

    #pragma unroll
    for (int j = 0; j < 4; j++) {
        float bb = bias[bn + tx + 16 * j];
        #pragma unroll
        for (int i = 0; i < 4; i++)
            C[(size_t)(bm + ty + 16 * i) * D_MODEL + bn + tx + 16 * j] = acc[i][j] + bb;
    }
}

// ---------------------------------------------------------------------------
// Flash attention, TF32 tensor cores, online softmax (FA2 style).
// Grid: (SEQ/64, NHEADS, NBATCH). Block: 128 threads = 4 warps.
// Warp w owns query rows [16w, 16w+16). Per warp: S tile 16x64 via 8x8
// m16n8k8 mmas; softmax in registers (quad shuffles); P routed through smem
// (warp-private region) back into A fragments for P@V.
// smem: Ks[64][68], Vs[64][68], Ps[64][68] (Ps doubles as Q staging).
// ---------------------------------------------------------------------------
__global__ __launch_bounds__(128)
void flash_attn_tf32(const float* __restrict__ Q,
                     const float* __restrict__ K,
                     const float* __restrict__ V,
                     float* __restrict__ O) {
    extern __shared__ float smf[];
    float* Ks = smf;              // 64*LDW
    float* Vs = Ks + 64 * LDW;    // 64*LDW
    float* Ps = Vs + 64 * LDW;    // 64*LDW (Q staging, then P)

    const int tid  = threadIdx.x;
    const int lane = tid & 31;
    const int w    = tid >> 5;        // warp 0..3
    const int g    = lane >> 2;       // groupID 0..7
    const int q4   = lane & 3;        // thread-in-group 0..3

    const int qblk = blockIdx.x;
    const int h    = blockIdx.y;
    const int n    = blockIdx.z;
    const int rowbase = n * SEQ + qblk * 64;
    const int col0    = h * HDIM;

    // ---- stage Q tile (pre-scaled by 1/sqrt(64), tf32-rounded) ----
    for (int i = tid; i < 64 * 16; i += 128) {
        int r = i >> 4, c4 = (i & 15) * 4;
        float4 v = *(const float4*)&Q[(size_t)(rowbase + r) * D_MODEL + col0 + c4];
        Ps[r * LDW + c4 + 0] = __uint_as_float(f2tf32(v.x * 0.125f));
        Ps[r * LDW + c4 + 1] = __uint_as_float(f2tf32(v.y * 0.125f));
        Ps[r * LDW + c4 + 2] = __uint_as_float(f2tf32(v.z * 0.125f));
        Ps[r * LDW + c4 + 3] = __uint_as_float(f2tf32(v.w * 0.125f));
    }
    __syncthreads();

    // Q fragments for all 8 k-steps (A of m16n8k8), kept in registers
    uint32_t qf[8][4];
    #pragma unroll
    for (int ks = 0; ks < 8; ks++) {
        qf[ks][0] = __float_as_uint(Ps[(w * 16 + g)     * LDW + ks * 8 + q4]);
        qf[ks][1] = __float_as_uint(Ps[(w * 16 + g + 8) * LDW + ks * 8 + q4]);
        qf[ks][2] = __float_as_uint(Ps[(w * 16 + g)     * LDW + ks * 8 + q4 + 4]);
        qf[ks][3] = __float_as_uint(Ps[(w * 16 + g + 8) * LDW + ks * 8 + q4 + 4]);
    }
    __syncthreads();

    float oc[8][4] = {};
    float m0 = -1e30f, m1 = -1e30f, l0 = 0.0f, l1 = 0.0f;

    for (int s0 = 0; s0 < SEQ; s0 += 64) {
        // ---- load K and V chunks (tf32-rounded) ----
        for (int i = tid; i < 64 * 16; i += 128) {
            int r = i >> 4, c4 = (i & 15) * 4;
            size_t goff = (size_t)(n * SEQ + s0 + r) * D_MODEL + col0 + c4;
            float4 kv = *(const float4*)&K[goff];
            Ks[r * LDW + c4 + 0] = __uint_as_float(f2tf32(kv.x));
            Ks[r * LDW + c4 + 1] = __uint_as_float(f2tf32(kv.y));
            Ks[r * LDW + c4 + 2] = __uint_as_float(f2tf32(kv.z));
            Ks[r * LDW + c4 + 3] = __uint_as_float(f2tf32(kv.w));
            float4 vv = *(const float4*)&V[goff];
            Vs[r * LDW + c4 + 0] = __uint_as_float(f2tf32(vv.x));
            Vs[r * LDW + c4 + 1] = __uint_as_float(f2tf32(vv.y));
            Vs[r * LDW + c4 + 2] = __uint_as_float(f2tf32(vv.z));
            Vs[r * LDW + c4 + 3] = __uint_as_float(f2tf32(vv.w));
        }
        __syncthreads();

        // ---- S = (Q*scale) @ K^T  : per warp 16x64 ----
        float sc[8][4] = {};
        #pragma unroll
        for (int ks = 0; ks < 8; ks++) {
            #pragma unroll
            for (int j = 0; j < 8; j++) {
                uint32_t b0 = __float_as_uint(Ks[(j * 8 + g) * LDW + ks * 8 + q4]);
                uint32_t b1 = __float_as_uint(Ks[(j * 8 + g) * LDW + ks * 8 + q4 + 4]);
                mma_tf32(sc[j], qf[ks][0], qf[ks][1], qf[ks][2], qf[ks][3], b0, b1);
            }
        }

        // ---- online softmax (rows r0 = g, r1 = g+8 within warp tile) ----
        float rm0 = -1e30f, rm1 = -1e30f;
        #pragma unroll
        for (int j = 0; j < 8; j++) {
            rm0 = fmaxf(rm0, fmaxf(sc[j][0], sc[j][1]));
            rm1 = fmaxf(rm1, fmaxf(sc[j][2], sc[j][3]));
        }
        rm0 = fmaxf(rm0, __shfl_xor_sync(0xffffffffu, rm0, 1));
        rm0 = fmaxf(rm0, __shfl_xor_sync(0xffffffffu, rm0, 2));
        rm1 = fmaxf(rm1, __shfl_xor_sync(0xffffffffu, rm1, 1));
        rm1 = fmaxf(rm1, __shfl_xor_sync(0xffffffffu, rm1, 2));

        float m0n = fmaxf(m0, rm0);
        float m1n = fmaxf(m1, rm1);
        float corr0 = __expf(m0 - m0n);
        float corr1 = __expf(m1 - m1n);
        m0 = m0n; m1 = m1n;

        float rs0 = 0.0f, rs1 = 0.0f;
        const int pr0 = (w * 16 + g) * LDW;
        const int pr1 = (w * 16 + g + 8) * LDW;
        #pragma unroll
        for (int j = 0; j < 8; j++) {
            float p0 = __expf(sc[j][0] - m0);
            float p1 = __expf(sc[j][1] - m0);
            float p2 = __expf(sc[j][2] - m1);
            float p3 = __expf(sc[j][3] - m1);
            rs0 += p0 + p1;
            rs1 += p2 + p3;
            int c = j * 8 + q4 * 2;
            Ps[pr0 + c]     = __uint_as_float(f2tf32(p0));
            Ps[pr0 + c + 1] = __uint_as_float(f2tf32(p1));
            Ps[pr1 + c]     = __uint_as_float(f2tf32(p2));
            Ps[pr1 + c + 1] = __uint_as_float(f2tf32(p3));
            oc[j][0] *= corr0; oc[j][1] *= corr0;
            oc[j][2] *= corr1; oc[j][3] *= corr1;
        }
        rs0 += __shfl_xor_sync(0xffffffffu, rs0, 1);
        rs0 += __shfl_xor_sync(0xffffffffu, rs0, 2);
        rs1 += __shfl_xor_sync(0xffffffffu, rs1, 1);
        rs1 += __shfl_xor_sync(0xffffffffu, rs1, 2);
        l0 = l0 * corr0 + rs0;
        l1 = l1 * corr1 + rs1;

        __syncwarp();   // P visible to whole warp before A-fragment reads

        // ---- O += P @ V ----
        #pragma unroll
        for (int ks = 0; ks < 8; ks++) {
            uint32_t a0 = __float_as_uint(Ps[pr0 + ks * 8 + q4]);
            uint32_t a1 = __float_as_uint(Ps[pr1 + ks * 8 + q4]);
            uint32_t a2 = __float_as_uint(Ps[pr0 + ks * 8 + q4 + 4]);
            uint32_t a3 = __float_as_uint(Ps[pr1 + ks * 8 + q4 + 4]);
            #pragma unroll
            for (int j = 0; j < 8; j++) {
                uint32_t b0 = __float_as_uint(Vs[(ks * 8 + q4)     * LDW + j * 8 + g]);
                uint32_t b1 = __float_as_uint(Vs[(ks * 8 + q4 + 4) * LDW + j * 8 + g]);
                mma_tf32(oc[j], a0, a1, a2, a3, b0, b1);
            }
        }
        __syncthreads();   // all warps done with Ks/Vs before next chunk load
    }

    // ---- normalize + store ----
    float il0 = 1.0f / l0;
    float il1 = 1.0f / l1;
    const size_t or0 = (size_t)(rowbase + w * 16 + g) * D_MODEL + col0;
    const size_t or1 = (size_t)(rowbase + w * 16 + g + 8) * D_MODEL + col0;
    #pragma unroll
    for (int j = 0; j < 8; j++) {
        int c = j * 8 + q4 * 2;
        float2 v0 = make_float2(oc[j][0] * il0, oc[j][1] * il0);
        float2 v1 = make_float2(oc[j][2] * il1, oc[j][3] * il1);
        *(float2*)&O[or0 + c] = v0;
        *(float2*)&O[or1 + c] = v1;
    }
}

// ---------------------------------------------------------------------------

extern "C" void kernel_launch(void* const* d_in, const int* in_sizes, int n_in,
                              void* d_out, int out_size) {
    const float* query = (const float*)d_in[0];
    const float* key   = (const float*)d_in[1];
    const float* value = (const float*)d_in[2];
    const float* Wq    = (const float*)d_in[3];
    const float* bq    = (const float*)d_in[4];
    const float* Wk    = (const float*)d_in[5];
    const float* bk    = (const float*)d_in[6];
    const float* Wv    = (const float*)d_in[7];
    const float* bv    = (const float*)d_in[8];
    const float* Wo    = (const float*)d_in[9];
    const float* bo    = (const float*)d_in[10];
    float* out = (float*)d_out;

    float *qp, *kp, *vp, *ao;
    cudaGetSymbolAddress((void**)&qp, g_Q);
    cudaGetSymbolAddress((void**)&kp, g_K);
    cudaGetSymbolAddress((void**)&vp, g_V);
    cudaGetSymbolAddress((void**)&ao, g_AO);

    dim3 gemm_grid(MROWS / 64, D_MODEL / 64);
    dim3 gemm_blk(256);

    gemm_abT_bias<<<gemm_grid, gemm_blk>>>(query, Wq, bq, qp, MROWS);
    gemm_abT_bias<<<gemm_grid, gemm_blk>>>(key,   Wk, bk, kp, MROWS);
    gemm_abT_bias<<<gemm_grid, gemm_blk>>>(value, Wv, bv, vp, MROWS);

    size_t flash_smem = 3 * 64 * LDW * sizeof(float);  // 52224 B
    cudaFuncSetAttribute(flash_attn_tf32,
                         cudaFuncAttributeMaxDynamicSharedMemorySize,
                         (int)flash_smem);
    dim3 flash_grid(SEQ / 64, NHEADS, NBATCH);
    flash_attn_tf32<<<flash_grid, 128, flash_smem>>>(qp, kp, vp, ao);

    gemm_abT_bias<<<gemm_grid, gemm_blk>>>(ao, Wo, bo, out, MROWS);
}

// round 3
// speedup vs baseline: 6.8338x; 1.6408x over previous
#include <cuda_runtime.h>
#include <cuda_fp16.h>
#include <math.h>
#include <stdint.h>

#define D_MODEL 512
#define NBATCH  2
#define SEQ     4096
#define NHEADS  8
#define HDIM    64
#define MROWS   (NBATCH * SEQ)   // 8192
#define LOG2E   1.44269504088896f

// Scratch: fp16 projected Q (pre-scaled), K, V-transposed-per-head; fp32 attn out.
__device__ __half g_Qh[MROWS * D_MODEL];
__device__ __half g_Kh[MROWS * D_MODEL];
__device__ __half g_Vt[MROWS * D_MODEL];   // [n][h][hd][kv]
__device__ float  g_AO[MROWS * D_MODEL];

// ---------------------------------------------------------------------------
// helpers
// ---------------------------------------------------------------------------
__device__ __forceinline__ uint32_t f2tf32(float f) {
    uint32_t u;
    asm("cvt.rna.tf32.f32 %0, %1;" : "=r"(u) : "f"(f));
    return u;
}
__device__ __forceinline__ float fast_ex2(float x) {
    float y;
    asm("ex2.approx.f32 %0, %1;" : "=f"(y) : "f"(x));
    return y;
}
__device__ __forceinline__ uint32_t hpack(float x, float y) {
    __half2 h = __floats2half2_rn(x, y);
    return *(uint32_t*)&h;
}
__device__ __forceinline__ void mma_tf32(float c[4],
                                         uint32_t a0, uint32_t a1, uint32_t a2, uint32_t a3,
                                         uint32_t b0, uint32_t b1) {
    asm volatile(
        "mma.sync.aligned.m16n8k8.row.col.f32.tf32.tf32.f32 "
        "{%0,%1,%2,%3}, {%4,%5,%6,%7}, {%8,%9}, {%0,%1,%2,%3};\n"
        : "+f"(c[0]), "+f"(c[1]), "+f"(c[2]), "+f"(c[3])
        : "r"(a0), "r"(a1), "r"(a2), "r"(a3), "r"(b0), "r"(b1));
}
__device__ __forceinline__ void mma_f16(float c[4],
                                        uint32_t a0, uint32_t a1, uint32_t a2, uint32_t a3,
                                        uint32_t b0, uint32_t b1) {
    asm volatile(
        "mma.sync.aligned.m16n8k16.row.col.f32.f16.f16.f32 "
        "{%0,%1,%2,%3}, {%4,%5,%6,%7}, {%8,%9}, {%0,%1,%2,%3};\n"
        : "+f"(c[0]), "+f"(c[1]), "+f"(c[2]), "+f"(c[3])
        : "r"(a0), "r"(a1), "r"(a2), "r"(a3), "r"(b0), "r"(b1));
}

// ---------------------------------------------------------------------------
// Split-TF32 GEMM: C[m,n] = sum_k A[m,k]*B[n,k] + bias[n], near-fp32 accuracy
// (a = ah+al, b = bh+bl; C = ah*bh + ah*bl + al*bh).
// Block 64x64, 128 threads (4 warps), k-chunk 32.
// mode 0: fp32 out.  mode 1: fp16 out, scaled.  mode 2: fp16 out transposed
// per-head: out[((nb*8+h)*64+hd)*4096 + kv].
// ---------------------------------------------------------------------------
__global__ __launch_bounds__(128)
void gemm_tf32_split(const float* __restrict__ A, const float* __restrict__ B,
                     const float* __restrict__ bias, void* __restrict__ out,
                     int mode, float scale) {
    __shared__ float Ah[64][36], Al[64][36], Bh[64][36], Bl[64][36];

    const int tid  = threadIdx.x;
    const int lane = tid & 31;
    const int w    = tid >> 5;
    const int g    = lane >> 2;
    const int q4   = lane & 3;
    const int bm   = blockIdx.x * 64;
    const int bn   = blockIdx.y * 64;

    float c[8][4] = {};

    for (int k0 = 0; k0 < D_MODEL; k0 += 32) {
        #pragma unroll
        for (int t = 0; t < 4; t++) {
            int idx = tid + t * 128;           // 0..511
            int r = idx >> 3, c4 = (idx & 7) * 4;
            float4 a4 = *(const float4*)&A[(size_t)(bm + r) * D_MODEL + k0 + c4];
            float4 b4 = *(const float4*)&B[(size_t)(bn + r) * D_MODEL + k0 + c4];
            float ax[4] = {a4.x, a4.y, a4.z, a4.w};
            float bx[4] = {b4.x, b4.y, b4.z, b4.w};
            #pragma unroll
            for (int d = 0; d < 4; d++) {
                float ah = __uint_as_float(f2tf32(ax[d]));
                Ah[r][c4 + d] = ah;
                Al[r][c4 + d] = __uint_as_float(f2tf32(ax[d] - ah));
                float bh = __uint_as_float(f2tf32(bx[d]));
                Bh[r][c4 + d] = bh;
                Bl[r][c4 + d] = __uint_as_float(f2tf32(bx[d] - bh));
            }
        }
        __syncthreads();

        #pragma unroll
        for (int ks = 0; ks < 4; ks++) {
            const int ar0 = w * 16 + g, ar1 = ar0 + 8, kc = ks * 8;
            uint32_t ah[4], al[4];
            ah[0] = __float_as_uint(Ah[ar0][kc + q4]);
            ah[1] = __float_as_uint(Ah[ar1][kc + q4]);
            ah[2] = __float_as_uint(Ah[ar0][kc + q4 + 4]);
            ah[3] = __float_as_uint(Ah[ar1][kc + q4 + 4]);
            al[0] = __float_as_uint(Al[ar0][kc + q4]);
            al[1] = __float_as_uint(Al[ar1][kc + q4]);
            al[2] = __float_as_uint(Al[ar0][kc + q4 + 4]);
            al[3] = __float_as_uint(Al[ar1][kc + q4 + 4]);
            #pragma unroll
            for (int j = 0; j < 8; j++) {
                uint32_t bh0 = __float_as_uint(Bh[j * 8 + g][kc + q4]);
                uint32_t bh1 = __float_as_uint(Bh[j * 8 + g][kc + q4 + 4]);
                uint32_t bl0 = __float_as_uint(Bl[j * 8 + g][kc + q4]);
                uint32_t bl1 = __float_as_uint(Bl[j * 8 + g][kc + q4 + 4]);
                mma_tf32(c[j], ah[0], ah[1], ah[2], ah[3], bh0, bh1);
                mma_tf32(c[j], ah[0], ah[1], ah[2], ah[3], bl0, bl1);
                mma_tf32(c[j], al[0], al[1], al[2], al[3], bh0, bh1);
            }
        }
        __syncthreads();
    }

    const int r0 = bm + w * 16 + g, r1 = r0 + 8;
    #pragma unroll
    for (int j = 0; j < 8; j++) {
        int col = bn + j * 8 + 2 * q4;
        float2 bb = *(const float2*)&bias[col];
        float v00 = (c[j][0] + bb.x) * scale, v01 = (c[j][1] + bb.y) * scale;
        float v10 = (c[j][2] + bb.x) * scale, v11 = (c[j][3] + bb.y) * scale;
        if (mode == 0) {
            *(float2*)&((float*)out)[(size_t)r0 * D_MODEL + col] = make_float2(v00, v01);
            *(float2*)&((float*)out)[(size_t)r1 * D_MODEL + col] = make_float2(v10, v11);
        } else if (mode == 1) {
            *(__half2*)&((__half*)out)[(size_t)r0 * D_MODEL + col] = __floats2half2_rn(v00, v01);
            *(__half2*)&((__half*)out)[(size_t)r1 * D_MODEL + col] = __floats2half2_rn(v10, v11);
        } else {
            int h = col >> 6, hd = col & 63;
            int nb0 = r0 >> 12, kv0 = r0 & 4095;
            int nb1 = r1 >> 12, kv1 = r1 & 4095;
            __half* O = (__half*)out;
            O[((size_t)(nb0 * NHEADS + h) * HDIM + hd)     * SEQ + kv0] = __float2half(v00);
            O[((size_t)(nb0 * NHEADS + h) * HDIM + hd + 1) * SEQ + kv0] = __float2half(v01);
            O[((size_t)(nb1 * NHEADS + h) * HDIM + hd)     * SEQ + kv1] = __float2half(v10);
            O[((size_t)(nb1 * NHEADS + h) * HDIM + hd + 1) * SEQ + kv1] = __float2half(v11);
        }
    }
}

// ---------------------------------------------------------------------------
// Flash attention, fp16 m16n8k16 tensor cores, exp2-domain online softmax.
// Q pre-scaled by 0.125*log2(e) in the projection. P stays in registers
// (fp16 C-fragment layout == A-fragment layout). V is pre-transposed per head.
// Grid (SEQ/64, NHEADS, NBATCH), 128 threads. smem: Ks[64][72], Vt[64][72] halfs.
// All fragment LDS are bank-conflict-free (stride 72 halfs -> bank 4g+q4+8ks).
// ---------------------------------------------------------------------------
__global__ __launch_bounds__(128)
void flash_attn_f16(const __half* __restrict__ Qh, const __half* __restrict__ Kh,
                    const __half* __restrict__ Vth, float* __restrict__ O) {
    __shared__ __half Ks[64 * 72];
    __shared__ __half Vt[64 * 72];

    const int tid  = threadIdx.x;
    const int lane = tid & 31;
    const int w    = tid >> 5;
    const int g    = lane >> 2;
    const int q4   = lane & 3;

    const int qblk = blockIdx.x;
    const int h    = blockIdx.y;
    const int n    = blockIdx.z;
    const int rowbase = n * SEQ + qblk * 64;
    const int col0    = h * HDIM;
    const size_t vbase = (size_t)(n * NHEADS + h) * HDIM * SEQ;

    // Q fragments for 4 k-steps, loaded directly from gmem (one-time)
    uint32_t qf[4][4];
    const int qr0 = rowbase + w * 16 + g, qr1 = qr0 + 8;
    #pragma unroll
    for (int ks = 0; ks < 4; ks++) {
        int cb = col0 + ks * 16 + 2 * q4;
        qf[ks][0] = *(const uint32_t*)&Qh[(size_t)qr0 * D_MODEL + cb];
        qf[ks][1] = *(const uint32_t*)&Qh[(size_t)qr1 * D_MODEL + cb];
        qf[ks][2] = *(const uint32_t*)&Qh[(size_t)qr0 * D_MODEL + cb + 8];
        qf[ks][3] = *(const uint32_t*)&Qh[(size_t)qr1 * D_MODEL + cb + 8];
    }

    float oc[8][4] = {};
    float m0 = -1e30f, m1 = -1e30f, l0 = 0.0f, l1 = 0.0f;

    for (int s0 = 0; s0 < SEQ; s0 += 64) {
        // load K [kv][hd] and Vt [hd][kv] chunks (fp16, vectorized)
        #pragma unroll
        for (int t = 0; t < 4; t++) {
            int idx = tid + t * 128;         // 0..511
            int r = idx >> 3, c8 = (idx & 7) * 8;
            uint4 kd = *(const uint4*)&Kh[(size_t)(n * SEQ + s0 + r) * D_MODEL + col0 + c8];
            *(uint4*)&Ks[r * 72 + c8] = kd;
            uint4 vd = *(const uint4*)&Vth[vbase + (size_t)r * SEQ + s0 + c8];
            *(uint4*)&Vt[r * 72 + c8] = vd;
        }
        __syncthreads();

        // S = Qs @ K^T (exp2 domain, scale folded into Q)
        float sc[8][4];
        #pragma unroll
        for (int j = 0; j < 8; j++) { sc[j][0] = sc[j][1] = sc[j][2] = sc[j][3] = 0.0f; }
        #pragma unroll
        for (int ks = 0; ks < 4; ks++) {
            #pragma unroll
            for (int j = 0; j < 8; j++) {
                uint32_t b0 = *(const uint32_t*)&Ks[(j * 8 + g) * 72 + ks * 16 + 2 * q4];
                uint32_t b1 = *(const uint32_t*)&Ks[(j * 8 + g) * 72 + ks * 16 + 2 * q4 + 8];
                mma_f16(sc[j], qf[ks][0], qf[ks][1], qf[ks][2], qf[ks][3], b0, b1);
            }
        }

        // online softmax (rows g, g+8); quad reductions
        float rm0 = -1e30f, rm1 = -1e30f;
        #pragma unroll
        for (int j = 0; j < 8; j++) {
            rm0 = fmaxf(rm0, fmaxf(sc[j][0], sc[j][1]));
            rm1 = fmaxf(rm1, fmaxf(sc[j][2], sc[j][3]));
        }
        rm0 = fmaxf(rm0, __shfl_xor_sync(0xffffffffu, rm0, 1));
        rm0 = fmaxf(rm0, __shfl_xor_sync(0xffffffffu, rm0, 2));
        rm1 = fmaxf(rm1, __shfl_xor_sync(0xffffffffu, rm1, 1));
        rm1 = fmaxf(rm1, __shfl_xor_sync(0xffffffffu, rm1, 2));
        float m0n = fmaxf(m0, rm0), m1n = fmaxf(m1, rm1);
        float corr0 = fast_ex2(m0 - m0n), corr1 = fast_ex2(m1 - m1n);
        m0 = m0n; m1 = m1n;

        float rs0 = 0.0f, rs1 = 0.0f;
        #pragma unroll
        for (int j = 0; j < 8; j++) {
            sc[j][0] = fast_ex2(sc[j][0] - m0);
            sc[j][1] = fast_ex2(sc[j][1] - m0);
            sc[j][2] = fast_ex2(sc[j][2] - m1);
            sc[j][3] = fast_ex2(sc[j][3] - m1);
            rs0 += sc[j][0] + sc[j][1];
            rs1 += sc[j][2] + sc[j][3];
            oc[j][0] *= corr0; oc[j][1] *= corr0;
            oc[j][2] *= corr1; oc[j][3] *= corr1;
        }
        rs0 += __shfl_xor_sync(0xffffffffu, rs0, 1);
        rs0 += __shfl_xor_sync(0xffffffffu, rs0, 2);
        rs1 += __shfl_xor_sync(0xffffffffu, rs1, 1);
        rs1 += __shfl_xor_sync(0xffffffffu, rs1, 2);
        l0 = l0 * corr0 + rs0;
        l1 = l1 * corr1 + rs1;

        // O += P @ V ; P converted in registers (C layout == A layout)
        #pragma unroll
        for (int ks = 0; ks < 4; ks++) {
            uint32_t pa0 = hpack(sc[2 * ks][0],     sc[2 * ks][1]);
            uint32_t pa1 = hpack(sc[2 * ks][2],     sc[2 * ks][3]);
            uint32_t pa2 = hpack(sc[2 * ks + 1][0], sc[2 * ks + 1][1]);
            uint32_t pa3 = hpack(sc[2 * ks + 1][2], sc[2 * ks + 1][3]);
            #pragma unroll
            for (int j = 0; j < 8; j++) {
                uint32_t b0 = *(const uint32_t*)&Vt[(j * 8 + g) * 72 + ks * 16 + 2 * q4];
                uint32_t b1 = *(const uint32_t*)&Vt[(j * 8 + g) * 72 + ks * 16 + 2 * q4 + 8];
                mma_f16(oc[j], pa0, pa1, pa2, pa3, b0, b1);
            }
        }
        __syncthreads();
    }

    // normalize + store fp32
    float il0 = 1.0f / l0, il1 = 1.0f / l1;
    const size_t or0 = (size_t)qr0 * D_MODEL + col0;
    const size_t or1 = (size_t)qr1 * D_MODEL + col0;
    #pragma unroll
    for (int j = 0; j < 8; j++) {
        int c = j * 8 + 2 * q4;
        *(float2*)&O[or0 + c] = make_float2(oc[j][0] * il0, oc[j][1] * il0);
        *(float2*)&O[or1 + c] = make_float2(oc[j][2] * il1, oc[j][3] * il1);
    }
}

// ---------------------------------------------------------------------------

extern "C" void kernel_launch(void* const* d_in, const int* in_sizes, int n_in,
                              void* d_out, int out_size) {
    const float* query = (const float*)d_in[0];
    const float* key   = (const float*)d_in[1];
    const float* value = (const float*)d_in[2];
    const float* Wq    = (const float*)d_in[3];
    const float* bq    = (const float*)d_in[4];
    const float* Wk    = (const float*)d_in[5];
    const float* bk    = (const float*)d_in[6];
    const float* Wv    = (const float*)d_in[7];
    const float* bv    = (const float*)d_in[8];
    const float* Wo    = (const float*)d_in[9];
    const float* bo    = (const float*)d_in[10];
    float* out = (float*)d_out;

    __half *qh, *kh, *vt;
    float *ao;
    cudaGetSymbolAddress((void**)&qh, g_Qh);
    cudaGetSymbolAddress((void**)&kh, g_Kh);
    cudaGetSymbolAddress((void**)&vt, g_Vt);
    cudaGetSymbolAddress((void**)&ao, g_AO);

    dim3 ggrid(MROWS / 64, D_MODEL / 64);

    gemm_tf32_split<<<ggrid, 128>>>(query, Wq, bq, qh, 1, 0.125f * LOG2E);
    gemm_tf32_split<<<ggrid, 128>>>(key,   Wk, bk, kh, 1, 1.0f);
    gemm_tf32_split<<<ggrid, 128>>>(value, Wv, bv, vt, 2, 1.0f);

    dim3 fgrid(SEQ / 64, NHEADS, NBATCH);
    flash_attn_f16<<<fgrid, 128>>>(qh, kh, vt, ao);

    gemm_tf32_split<<<ggrid, 128>>>(ao, Wo, bo, out, 0, 1.0f);
}

// round 5
// speedup vs baseline: 9.6202x; 1.4077x over previous
#include <cuda_runtime.h>
#include <cuda_fp16.h>
#include <cuda_bf16.h>
#include <math.h>
#include <stdint.h>

#define D_MODEL 512
#define NBATCH  2
#define SEQ     4096
#define NHEADS  8
#define HDIM    64
#define MROWS   (NBATCH * SEQ)   // 8192
#define LOG2E   1.44269504088896f

// ---- scratch -------------------------------------------------------------
// bf16 hi/lo splits of the three inputs and four weights
__device__ __nv_bfloat16 g_qh[MROWS * D_MODEL], g_ql[MROWS * D_MODEL];
__device__ __nv_bfloat16 g_kh[MROWS * D_MODEL], g_kl[MROWS * D_MODEL];
__device__ __nv_bfloat16 g_vh[MROWS * D_MODEL], g_vl[MROWS * D_MODEL];
__device__ __nv_bfloat16 g_Wqh[D_MODEL * D_MODEL], g_Wql[D_MODEL * D_MODEL];
__device__ __nv_bfloat16 g_Wkh[D_MODEL * D_MODEL], g_Wkl[D_MODEL * D_MODEL];
__device__ __nv_bfloat16 g_Wvh[D_MODEL * D_MODEL], g_Wvl[D_MODEL * D_MODEL];
__device__ __nv_bfloat16 g_Woh[D_MODEL * D_MODEL], g_Wol[D_MODEL * D_MODEL];
// fp16 projected Q (pre-scaled), K, V-transposed-per-head
__device__ __half g_Qh[MROWS * D_MODEL];
__device__ __half g_Kh[MROWS * D_MODEL];
__device__ __half g_Vt[MROWS * D_MODEL];   // [n][h][hd][kv]
// attention output as bf16 hi/lo (feeds the final GEMM directly)
__device__ __nv_bfloat16 g_AOh[MROWS * D_MODEL], g_AOl[MROWS * D_MODEL];

// ---- helpers -------------------------------------------------------------
__device__ __forceinline__ float fast_ex2(float x) {
    float y;
    asm("ex2.approx.f32 %0, %1;" : "=f"(y) : "f"(x));
    return y;
}
__device__ __forceinline__ uint32_t hpack(float x, float y) {
    __half2 h = __floats2half2_rn(x, y);
    return *(uint32_t*)&h;
}
__device__ __forceinline__ void mma_f16(float c[4],
                                        uint32_t a0, uint32_t a1, uint32_t a2, uint32_t a3,
                                        uint32_t b0, uint32_t b1) {
    asm volatile(
        "mma.sync.aligned.m16n8k16.row.col.f32.f16.f16.f32 "
        "{%0,%1,%2,%3}, {%4,%5,%6,%7}, {%8,%9}, {%0,%1,%2,%3};\n"
        : "+f"(c[0]), "+f"(c[1]), "+f"(c[2]), "+f"(c[3])
        : "r"(a0), "r"(a1), "r"(a2), "r"(a3), "r"(b0), "r"(b1));
}
__device__ __forceinline__ void mma_bf16(float c[4],
                                         uint32_t a0, uint32_t a1, uint32_t a2, uint32_t a3,
                                         uint32_t b0, uint32_t b1) {
    asm volatile(
        "mma.sync.aligned.m16n8k16.row.col.f32.bf16.bf16.f32 "
        "{%0,%1,%2,%3}, {%4,%5,%6,%7}, {%8,%9}, {%0,%1,%2,%3};\n"
        : "+f"(c[0]), "+f"(c[1]), "+f"(c[2]), "+f"(c[3])
        : "r"(a0), "r"(a1), "r"(a2), "r"(a3), "r"(b0), "r"(b1));
}
__device__ __forceinline__ void ldsm_x4(uint32_t r[4], uint32_t saddr) {
    asm volatile("ldmatrix.sync.aligned.m8n8.x4.shared.b16 {%0,%1,%2,%3}, [%4];"
                 : "=r"(r[0]), "=r"(r[1]), "=r"(r[2]), "=r"(r[3]) : "r"(saddr));
}

// ---------------------------------------------------------------------------
// Elementwise fp32 -> bf16 hi/lo split (4 elements / thread)
// ---------------------------------------------------------------------------
__global__ __launch_bounds__(256)
void cvt_split(const float* __restrict__ src, __nv_bfloat16* __restrict__ hi,
               __nv_bfloat16* __restrict__ lo, int n4) {
    int i = blockIdx.x * 256 + threadIdx.x;
    if (i >= n4) return;
    float4 v = ((const float4*)src)[i];
    __nv_bfloat162 h0 = __floats2bfloat162_rn(v.x, v.y);
    __nv_bfloat162 h1 = __floats2bfloat162_rn(v.z, v.w);
    ((__nv_bfloat162*)hi)[2 * i]     = h0;
    ((__nv_bfloat162*)hi)[2 * i + 1] = h1;
    __nv_bfloat162 l0 = __floats2bfloat162_rn(v.x - __bfloat162float(h0.x),
                                              v.y - __bfloat162float(h0.y));
    __nv_bfloat162 l1 = __floats2bfloat162_rn(v.z - __bfloat162float(h1.x),
                                              v.w - __bfloat162float(h1.y));
    ((__nv_bfloat162*)lo)[2 * i]     = l0;
    ((__nv_bfloat162*)lo)[2 * i + 1] = l1;
}

// ---------------------------------------------------------------------------
// Split-bf16 GEMM: C[m,n] = sum_k A[m,k]*B[n,k] + bias[n]
// A,B pre-split into bf16 hi/lo. 3-term: ah*bh + ah*bl + al*bh (fp32 accum).
// Block 64x64, 128 threads, k-chunk 32, all fragment loads via ldmatrix.
// mode 0: fp32 out.  mode 1: fp16 out, scaled.  mode 2: fp16 out transposed
// per-head: out[((nb*8+h)*64+hd)*4096 + kv].
// ---------------------------------------------------------------------------
__global__ __launch_bounds__(128)
void gemm_bf16split(const __nv_bfloat16* __restrict__ Ah, const __nv_bfloat16* __restrict__ Al,
                    const __nv_bfloat16* __restrict__ Bh, const __nv_bfloat16* __restrict__ Bl,
                    const float* __restrict__ bias, void* __restrict__ out,
                    int mode, float scale) {
    // packed as uint32 (bf16 pair); row stride 20 words (16 data + 4 pad)
    __shared__ uint32_t AsH[64][20], AsL[64][20], BsH[64][20], BsL[64][20];

    const int tid  = threadIdx.x;
    const int lane = tid & 31;
    const int w    = tid >> 5;
    const int g    = lane >> 2;
    const int q4   = lane & 3;
    const int bm   = blockIdx.x * 64;
    const int bn   = blockIdx.y * 64;

    const uint32_t ah_b = (uint32_t)__cvta_generic_to_shared(&AsH[0][0]);
    const uint32_t al_b = (uint32_t)__cvta_generic_to_shared(&AsL[0][0]);
    const uint32_t bh_b = (uint32_t)__cvta_generic_to_shared(&BsH[0][0]);
    const uint32_t bl_b = (uint32_t)__cvta_generic_to_shared(&BsL[0][0]);

    // per-lane ldmatrix byte offsets
    const uint32_t a_off = (uint32_t)((((lane & 15) + w * 16) * 20 + (lane >> 4) * 4) * 4);
    const int lm_row = ((lane >> 4) << 3) | (lane & 7);
    const uint32_t b_off = (uint32_t)((lm_row * 20 + ((lane >> 3) & 1) * 4) * 4);

    float c[8][4] = {};

    for (int k0 = 0; k0 < D_MODEL; k0 += 32) {
        #pragma unroll
        for (int t = 0; t < 2; t++) {
            int idx = tid + t * 128;           // 0..255
            int r = idx >> 2, q = (idx & 3) * 8;
            *(uint4*)&AsH[r][(idx & 3) * 4] = *(const uint4*)&Ah[(size_t)(bm + r) * D_MODEL + k0 + q];
            *(uint4*)&AsL[r][(idx & 3) * 4] = *(const uint4*)&Al[(size_t)(bm + r) * D_MODEL + k0 + q];
            *(uint4*)&BsH[r][(idx & 3) * 4] = *(const uint4*)&Bh[(size_t)(bn + r) * D_MODEL + k0 + q];
            *(uint4*)&BsL[r][(idx & 3) * 4] = *(const uint4*)&Bl[(size_t)(bn + r) * D_MODEL + k0 + q];
        }
        __syncthreads();

        #pragma unroll
        for (int ks = 0; ks < 2; ks++) {
            uint32_t ah[4], al[4];
            ldsm_x4(ah, ah_b + a_off + ks * 32);
            ldsm_x4(al, al_b + a_off + ks * 32);
            #pragma unroll
            for (int j2 = 0; j2 < 4; j2++) {
                uint32_t bh[4], bl[4];
                uint32_t jo = b_off + (uint32_t)(j2 * 1280 + ks * 32);
                ldsm_x4(bh, bh_b + jo);
                ldsm_x4(bl, bl_b + jo);
                mma_bf16(c[2 * j2],     ah[0], ah[1], ah[2], ah[3], bh[0], bh[1]);
                mma_bf16(c[2 * j2],     ah[0], ah[1], ah[2], ah[3], bl[0], bl[1]);
                mma_bf16(c[2 * j2],     al[0], al[1], al[2], al[3], bh[0], bh[1]);
                mma_bf16(c[2 * j2 + 1], ah[0], ah[1], ah[2], ah[3], bh[2], bh[3]);
                mma_bf16(c[2 * j2 + 1], ah[0], ah[1], ah[2], ah[3], bl[2], bl[3]);
                mma_bf16(c[2 * j2 + 1], al[0], al[1], al[2], al[3], bh[2], bh[3]);
            }
        }
        __syncthreads();
    }

    const int r0 = bm + w * 16 + g, r1 = r0 + 8;
    #pragma unroll
    for (int j = 0; j < 8; j++) {
        int col = bn + j * 8 + 2 * q4;
        float2 bb = *(const float2*)&bias[col];
        float v00 = (c[j][0] + bb.x) * scale, v01 = (c[j][1] + bb.y) * scale;
        float v10 = (c[j][2] + bb.x) * scale, v11 = (c[j][3] + bb.y) * scale;
        if (mode == 0) {
            *(float2*)&((float*)out)[(size_t)r0 * D_MODEL + col] = make_float2(v00, v01);
            *(float2*)&((float*)out)[(size_t)r1 * D_MODEL + col] = make_float2(v10, v11);
        } else if (mode == 1) {
            *(__half2*)&((__half*)out)[(size_t)r0 * D_MODEL + col] = __floats2half2_rn(v00, v01);
            *(__half2*)&((__half*)out)[(size_t)r1 * D_MODEL + col] = __floats2half2_rn(v10, v11);
        } else {
            int h = col >> 6, hd = col & 63;
            int nb0 = r0 >> 12, kv0 = r0 & 4095;
            int nb1 = r1 >> 12, kv1 = r1 & 4095;
            __half* O = (__half*)out;
            O[((size_t)(nb0 * NHEADS + h) * HDIM + hd)     * SEQ + kv0] = __float2half(v00);
            O[((size_t)(nb0 * NHEADS + h) * HDIM + hd + 1) * SEQ + kv0] = __float2half(v01);
            O[((size_t)(nb1 * NHEADS + h) * HDIM + hd)     * SEQ + kv1] = __float2half(v10);
            O[((size_t)(nb1 * NHEADS + h) * HDIM + hd + 1) * SEQ + kv1] = __float2half(v11);
        }
    }
}

// ---------------------------------------------------------------------------
// Flash attention, fp16 m16n8k16, ldmatrix fragments, exp2-domain softmax.
// Grid (SEQ/128, NHEADS, NBATCH), 256 threads (8 warps, 16 q-rows each).
// K/V chunk 64; smem Ks[64][72], Vt[64][72] halfs shared by all warps.
// Output written as bf16 hi/lo pair (feeds final GEMM directly).
// ---------------------------------------------------------------------------
__global__ __launch_bounds__(256)
void flash_attn_f16(const __half* __restrict__ Qh, const __half* __restrict__ Kh,
                    const __half* __restrict__ Vth,
                    __nv_bfloat16* __restrict__ AOh, __nv_bfloat16* __restrict__ AOl) {
    __shared__ __half Ks[64 * 72];
    __shared__ __half Vt[64 * 72];

    const int tid  = threadIdx.x;
    const int lane = tid & 31;
    const int w    = tid >> 5;
    const int g    = lane >> 2;
    const int q4   = lane & 3;

    const int qblk = blockIdx.x;
    const int h    = blockIdx.y;
    const int n    = blockIdx.z;
    const int rowbase = n * SEQ + qblk * 128;
    const int col0    = h * HDIM;
    const size_t vbase = (size_t)(n * NHEADS + h) * HDIM * SEQ;

    const uint32_t ks_b = (uint32_t)__cvta_generic_to_shared(Ks);
    const uint32_t vt_b = (uint32_t)__cvta_generic_to_shared(Vt);
    const int lm_row = ((lane >> 4) << 3) | (lane & 7);
    const uint32_t lm_off = (uint32_t)((lm_row * 72 + (((lane >> 3) & 1) << 3)) * 2);

    // Q fragments (4 k-steps), one-time gmem load
    uint32_t qf[4][4];
    const int qr0 = rowbase + w * 16 + g, qr1 = qr0 + 8;
    #pragma unroll
    for (int ks = 0; ks < 4; ks++) {
        int cb = col0 + ks * 16 + 2 * q4;
        qf[ks][0] = *(const uint32_t*)&Qh[(size_t)qr0 * D_MODEL + cb];
        qf[ks][1] = *(const uint32_t*)&Qh[(size_t)qr1 * D_MODEL + cb];
        qf[ks][2] = *(const uint32_t*)&Qh[(size_t)qr0 * D_MODEL + cb + 8];
        qf[ks][3] = *(const uint32_t*)&Qh[(size_t)qr1 * D_MODEL + cb + 8];
    }

    float oc[8][4] = {};
    float m0 = -1e30f, m1 = -1e30f, l0 = 0.0f, l1 = 0.0f;

    for (int s0 = 0; s0 < SEQ; s0 += 64) {
        #pragma unroll
        for (int t = 0; t < 2; t++) {
            int idx = tid + t * 256;          // 0..511
            int r = idx >> 3, c8 = (idx & 7) * 8;
            *(uint4*)&Ks[r * 72 + c8] = *(const uint4*)&Kh[(size_t)(n * SEQ + s0 + r) * D_MODEL + col0 + c8];
            *(uint4*)&Vt[r * 72 + c8] = *(const uint4*)&Vth[vbase + (size_t)r * SEQ + s0 + c8];
        }
        __syncthreads();

        // S = Qs @ K^T
        float sc[8][4];
        #pragma unroll
        for (int j = 0; j < 8; j++) { sc[j][0] = sc[j][1] = sc[j][2] = sc[j][3] = 0.0f; }
        #pragma unroll
        for (int ks = 0; ks < 4; ks++) {
            #pragma unroll
            for (int j2 = 0; j2 < 4; j2++) {
                uint32_t b[4];
                ldsm_x4(b, ks_b + lm_off + (uint32_t)(j2 * 2304 + ks * 32));
                mma_f16(sc[2 * j2],     qf[ks][0], qf[ks][1], qf[ks][2], qf[ks][3], b[0], b[1]);
                mma_f16(sc[2 * j2 + 1], qf[ks][0], qf[ks][1], qf[ks][2], qf[ks][3], b[2], b[3]);
            }
        }

        // online softmax (rows g, g+8)
        float rm0 = -1e30f, rm1 = -1e30f;
        #pragma unroll
        for (int j = 0; j < 8; j++) {
            rm0 = fmaxf(rm0, fmaxf(sc[j][0], sc[j][1]));
            rm1 = fmaxf(rm1, fmaxf(sc[j][2], sc[j][3]));
        }
        rm0 = fmaxf(rm0, __shfl_xor_sync(0xffffffffu, rm0, 1));
        rm0 = fmaxf(rm0, __shfl_xor_sync(0xffffffffu, rm0, 2));
        rm1 = fmaxf(rm1, __shfl_xor_sync(0xffffffffu, rm1, 1));
        rm1 = fmaxf(rm1, __shfl_xor_sync(0xffffffffu, rm1, 2));
        float m0n = fmaxf(m0, rm0), m1n = fmaxf(m1, rm1);
        float corr0 = fast_ex2(m0 - m0n), corr1 = fast_ex2(m1 - m1n);
        m0 = m0n; m1 = m1n;

        float rs0 = 0.0f, rs1 = 0.0f;
        #pragma unroll
        for (int j = 0; j < 8; j++) {
            sc[j][0] = fast_ex2(sc[j][0] - m0);
            sc[j][1] = fast_ex2(sc[j][1] - m0);
            sc[j][2] = fast_ex2(sc[j][2] - m1);
            sc[j][3] = fast_ex2(sc[j][3] - m1);
            rs0 += sc[j][0] + sc[j][1];
            rs1 += sc[j][2] + sc[j][3];
            oc[j][0] *= corr0; oc[j][1] *= corr0;
            oc[j][2] *= corr1; oc[j][3] *= corr1;
        }
        rs0 += __shfl_xor_sync(0xffffffffu, rs0, 1);
        rs0 += __shfl_xor_sync(0xffffffffu, rs0, 2);
        rs1 += __shfl_xor_sync(0xffffffffu, rs1, 1);
        rs1 += __shfl_xor_sync(0xffffffffu, rs1, 2);
        l0 = l0 * corr0 + rs0;
        l1 = l1 * corr1 + rs1;

        // O += P @ V  (P in registers: C layout == A layout)
        #pragma unroll
        for (int ks = 0; ks < 4; ks++) {
            uint32_t pa0 = hpack(sc[2 * ks][0],     sc[2 * ks][1]);
            uint32_t pa1 = hpack(sc[2 * ks][2],     sc[2 * ks][3]);
            uint32_t pa2 = hpack(sc[2 * ks + 1][0], sc[2 * ks + 1][1]);
            uint32_t pa3 = hpack(sc[2 * ks + 1][2], sc[2 * ks + 1][3]);
            #pragma unroll
            for (int j2 = 0; j2 < 4; j2++) {
                uint32_t b[4];
                ldsm_x4(b, vt_b + lm_off + (uint32_t)(j2 * 2304 + ks * 32));
                mma_f16(oc[2 * j2],     pa0, pa1, pa2, pa3, b[0], b[1]);
                mma_f16(oc[2 * j2 + 1], pa0, pa1, pa2, pa3, b[2], b[3]);
            }
        }
        __syncthreads();
    }

    // normalize + bf16 hi/lo store
    float il0 = 1.0f / l0, il1 = 1.0f / l1;
    const size_t or0 = (size_t)qr0 * D_MODEL + col0;
    const size_t or1 = (size_t)qr1 * D_MODEL + col0;
    #pragma unroll
    for (int j = 0; j < 8; j++) {
        int c = j * 8 + 2 * q4;
        float v00 = oc[j][0] * il0, v01 = oc[j][1] * il0;
        float v10 = oc[j][2] * il1, v11 = oc[j][3] * il1;
        __nv_bfloat162 h0 = __floats2bfloat162_rn(v00, v01);
        __nv_bfloat162 h1 = __floats2bfloat162_rn(v10, v11);
        *(__nv_bfloat162*)&AOh[or0 + c] = h0;
        *(__nv_bfloat162*)&AOh[or1 + c] = h1;
        *(__nv_bfloat162*)&AOl[or0 + c] =
            __floats2bfloat162_rn(v00 - __bfloat162float(h0.x), v01 - __bfloat162float(h0.y));
        *(__nv_bfloat162*)&AOl[or1 + c] =
            __floats2bfloat162_rn(v10 - __bfloat162float(h1.x), v11 - __bfloat162float(h1.y));
    }
}

// ---------------------------------------------------------------------------

extern "C" void kernel_launch(void* const* d_in, const int* in_sizes, int n_in,
                              void* d_out, int out_size) {
    const float* query = (const float*)d_in[0];
    const float* key   = (const float*)d_in[1];
    const float* value = (const float*)d_in[2];
    const float* Wq    = (const float*)d_in[3];
    const float* bq    = (const float*)d_in[4];
    const float* Wk    = (const float*)d_in[5];
    const float* bk    = (const float*)d_in[6];
    const float* Wv    = (const float*)d_in[7];
    const float* bv    = (const float*)d_in[8];
    const float* Wo    = (const float*)d_in[9];
    const float* bo    = (const float*)d_in[10];
    float* out = (float*)d_out;

    __nv_bfloat16 *qh, *ql, *kh, *kl, *vh, *vl;
    __nv_bfloat16 *wqh, *wql, *wkh, *wkl, *wvh, *wvl, *woh, *wol;
    __nv_bfloat16 *aoh, *aol;
    __half *Qh, *Kh, *Vt;
    cudaGetSymbolAddress((void**)&qh, g_qh);   cudaGetSymbolAddress((void**)&ql, g_ql);
    cudaGetSymbolAddress((void**)&kh, g_kh);   cudaGetSymbolAddress((void**)&kl, g_kl);
    cudaGetSymbolAddress((void**)&vh, g_vh);   cudaGetSymbolAddress((void**)&vl, g_vl);
    cudaGetSymbolAddress((void**)&wqh, g_Wqh); cudaGetSymbolAddress((void**)&wql, g_Wql);
    cudaGetSymbolAddress((void**)&wkh, g_Wkh); cudaGetSymbolAddress((void**)&wkl, g_Wkl);
    cudaGetSymbolAddress((void**)&wvh, g_Wvh); cudaGetSymbolAddress((void**)&wvl, g_Wvl);
    cudaGetSymbolAddress((void**)&woh, g_Woh); cudaGetSymbolAddress((void**)&wol, g_Wol);
    cudaGetSymbolAddress((void**)&aoh, g_AOh); cudaGetSymbolAddress((void**)&aol, g_AOl);
    cudaGetSymbolAddress((void**)&Qh, g_Qh);
    cudaGetSymbolAddress((void**)&Kh, g_Kh);
    cudaGetSymbolAddress((void**)&Vt, g_Vt);

    const int n4_in = MROWS * D_MODEL / 4;       // 1048576
    const int n4_w  = D_MODEL * D_MODEL / 4;     // 65536
    cvt_split<<<n4_in / 256, 256>>>(query, qh, ql, n4_in);
    cvt_split<<<n4_in / 256, 256>>>(key,   kh, kl, n4_in);
    cvt_split<<<n4_in / 256, 256>>>(value, vh, vl, n4_in);
    cvt_split<<<n4_w / 256, 256>>>(Wq, wqh, wql, n4_w);
    cvt_split<<<n4_w / 256, 256>>>(Wk, wkh, wkl, n4_w);
    cvt_split<<<n4_w / 256, 256>>>(Wv, wvh, wvl, n4_w);
    cvt_split<<<n4_w / 256, 256>>>(Wo, woh, wol, n4_w);

    dim3 ggrid(MROWS / 64, D_MODEL / 64);
    gemm_bf16split<<<ggrid, 128>>>(qh, ql, wqh, wql, bq, Qh, 1, 0.125f * LOG2E);
    gemm_bf16split<<<ggrid, 128>>>(kh, kl, wkh, wkl, bk, Kh, 1, 1.0f);
    gemm_bf16split<<<ggrid, 128>>>(vh, vl, wvh, wvl, bv, Vt, 2, 1.0f);

    dim3 fgrid(SEQ / 128, NHEADS, NBATCH);
    flash_attn_f16<<<fgrid, 256>>>(Qh, Kh, Vt, aoh, aol);

    gemm_bf16split<<<ggrid, 128>>>(aoh, aol, woh, wol, bo, out, 0, 1.0f);
}

// round 6
// speedup vs baseline: 10.8984x; 1.1329x over previous
#include <cuda_runtime.h>
#include <cuda_fp16.h>
#include <cuda_bf16.h>
#include <math.h>
#include <stdint.h>

#define D_MODEL 512
#define NBATCH  2
#define SEQ     4096
#define NHEADS  8
#define HDIM    64
#define MROWS   (NBATCH * SEQ)   // 8192
#define LOG2E   1.44269504088896f

// ---- scratch -------------------------------------------------------------
__device__ __nv_bfloat16 g_qh[MROWS * D_MODEL], g_ql[MROWS * D_MODEL];
__device__ __nv_bfloat16 g_kh[MROWS * D_MODEL], g_kl[MROWS * D_MODEL];
__device__ __nv_bfloat16 g_vh[MROWS * D_MODEL], g_vl[MROWS * D_MODEL];
__device__ __nv_bfloat16 g_Wqh[D_MODEL * D_MODEL], g_Wql[D_MODEL * D_MODEL];
__device__ __nv_bfloat16 g_Wkh[D_MODEL * D_MODEL], g_Wkl[D_MODEL * D_MODEL];
__device__ __nv_bfloat16 g_Wvh[D_MODEL * D_MODEL], g_Wvl[D_MODEL * D_MODEL];
__device__ __nv_bfloat16 g_Woh[D_MODEL * D_MODEL], g_Wol[D_MODEL * D_MODEL];
// fp16 projected Q (pre-scaled), K, V (all [token][dmodel] row-major)
__device__ __half g_Qh[MROWS * D_MODEL];
__device__ __half g_Kh[MROWS * D_MODEL];
__device__ __half g_Vh[MROWS * D_MODEL];
// attention output as bf16 hi/lo (feeds final GEMM directly)
__device__ __nv_bfloat16 g_AOh[MROWS * D_MODEL], g_AOl[MROWS * D_MODEL];

// ---- helpers -------------------------------------------------------------
__device__ __forceinline__ float fast_ex2(float x) {
    float y;
    asm("ex2.approx.f32 %0, %1;" : "=f"(y) : "f"(x));
    return y;
}
__device__ __forceinline__ uint32_t hpack(float x, float y) {
    __half2 h = __floats2half2_rn(x, y);
    return *(uint32_t*)&h;
}
__device__ __forceinline__ void mma_f16(float c[4],
                                        uint32_t a0, uint32_t a1, uint32_t a2, uint32_t a3,
                                        uint32_t b0, uint32_t b1) {
    asm volatile(
        "mma.sync.aligned.m16n8k16.row.col.f32.f16.f16.f32 "
        "{%0,%1,%2,%3}, {%4,%5,%6,%7}, {%8,%9}, {%0,%1,%2,%3};\n"
        : "+f"(c[0]), "+f"(c[1]), "+f"(c[2]), "+f"(c[3])
        : "r"(a0), "r"(a1), "r"(a2), "r"(a3), "r"(b0), "r"(b1));
}
__device__ __forceinline__ void mma_bf16(float c[4],
                                         uint32_t a0, uint32_t a1, uint32_t a2, uint32_t a3,
                                         uint32_t b0, uint32_t b1) {
    asm volatile(
        "mma.sync.aligned.m16n8k16.row.col.f32.bf16.bf16.f32 "
        "{%0,%1,%2,%3}, {%4,%5,%6,%7}, {%8,%9}, {%0,%1,%2,%3};\n"
        : "+f"(c[0]), "+f"(c[1]), "+f"(c[2]), "+f"(c[3])
        : "r"(a0), "r"(a1), "r"(a2), "r"(a3), "r"(b0), "r"(b1));
}
__device__ __forceinline__ void ldsm_x4(uint32_t r[4], uint32_t saddr) {
    asm volatile("ldmatrix.sync.aligned.m8n8.x4.shared.b16 {%0,%1,%2,%3}, [%4];"
                 : "=r"(r[0]), "=r"(r[1]), "=r"(r[2]), "=r"(r[3]) : "r"(saddr));
}
__device__ __forceinline__ void ldsm_x4_t(uint32_t r[4], uint32_t saddr) {
    asm volatile("ldmatrix.sync.aligned.m8n8.x4.trans.shared.b16 {%0,%1,%2,%3}, [%4];"
                 : "=r"(r[0]), "=r"(r[1]), "=r"(r[2]), "=r"(r[3]) : "r"(saddr));
}
__device__ __forceinline__ void cp16(uint32_t saddr, const void* gaddr) {
    asm volatile("cp.async.cg.shared.global [%0], [%1], 16;" :: "r"(saddr), "l"(gaddr));
}

// ---------------------------------------------------------------------------
// Elementwise fp32 -> bf16 hi/lo split
// ---------------------------------------------------------------------------
__global__ __launch_bounds__(256)
void cvt_split(const float* __restrict__ src, __nv_bfloat16* __restrict__ hi,
               __nv_bfloat16* __restrict__ lo, int n4) {
    int i = blockIdx.x * 256 + threadIdx.x;
    if (i >= n4) return;
    float4 v = ((const float4*)src)[i];
    __nv_bfloat162 h0 = __floats2bfloat162_rn(v.x, v.y);
    __nv_bfloat162 h1 = __floats2bfloat162_rn(v.z, v.w);
    ((__nv_bfloat162*)hi)[2 * i]     = h0;
    ((__nv_bfloat162*)hi)[2 * i + 1] = h1;
    ((__nv_bfloat162*)lo)[2 * i] = __floats2bfloat162_rn(
        v.x - __bfloat162float(h0.x), v.y - __bfloat162float(h0.y));
    ((__nv_bfloat162*)lo)[2 * i + 1] = __floats2bfloat162_rn(
        v.z - __bfloat162float(h1.x), v.w - __bfloat162float(h1.y));
}

// ---------------------------------------------------------------------------
// Split-bf16 GEMM, 128x128 tile, 256 threads, double-buffered cp.async.
// C[m,n] = sum_k A[m,k]*B[n,k] + bias[n]; 3-term: ah*bh + ah*bl + al*bh.
// Warp grid 2(m) x 4(n); warp tile 64x32 (4 m-frags x 4 n-frags).
// smem per stage: 4 arrays [128 rows][20 words] (16 data + 4 pad), 2 stages.
// mode 0: fp32 out.  mode 1: fp16 out, scaled.
// ---------------------------------------------------------------------------
#define GLDW 20
#define ARRW (128 * GLDW)          // words per array   = 2560
#define STGW (4 * ARRW)            // words per stage   = 10240
#define GSMEM_BYTES (2 * STGW * 4) // 81920

__global__ __launch_bounds__(256, 1)
void gemm_bf16split2(const __nv_bfloat16* __restrict__ Ah, const __nv_bfloat16* __restrict__ Al,
                     const __nv_bfloat16* __restrict__ Bh, const __nv_bfloat16* __restrict__ Bl,
                     const float* __restrict__ bias, void* __restrict__ out,
                     int mode, float scale) {
    extern __shared__ uint32_t sg[];

    const int tid  = threadIdx.x;
    const int lane = tid & 31;
    const int w    = tid >> 5;
    const int wm   = w >> 2;        // 0..1
    const int wn   = w & 3;         // 0..3
    const int g    = lane >> 2;
    const int q4   = lane & 3;
    const int bm   = blockIdx.x * 128;
    const int bn   = blockIdx.y * 128;

    const uint32_t s_b = (uint32_t)__cvta_generic_to_shared(sg);

    // per-lane ldmatrix byte offsets (validated pattern from R4)
    const uint32_t a_off = (uint32_t)(((wm * 64 + (lane & 15)) * GLDW + (lane >> 4) * 4) * 4);
    const int lm_row = ((lane >> 4) << 3) | (lane & 7);
    const uint32_t b_off = (uint32_t)(((wn * 32 + lm_row) * GLDW + ((lane >> 3) & 1) * 4) * 4);

    // cp.async load of one 32-wide k-chunk into stage s
    const int lr = tid >> 2;               // 0..63 (+64 on t=1)
    const int lw = (tid & 3) * 4;          // word col 0,4,8,12
    const int lc = (tid & 3) * 8;          // bf16 col

    float c[4][4][4] = {};

    int k0 = 0;
    // prologue: load chunk 0 into stage 0
    {
        #pragma unroll
        for (int t = 0; t < 2; t++) {
            int r = lr + t * 64;
            uint32_t so = s_b + (uint32_t)((r * GLDW + lw) * 4);
            cp16(so,                (const void*)&Ah[(size_t)(bm + r) * D_MODEL + lc]);
            cp16(so + ARRW * 4,     (const void*)&Al[(size_t)(bm + r) * D_MODEL + lc]);
            cp16(so + 2 * ARRW * 4, (const void*)&Bh[(size_t)(bn + r) * D_MODEL + lc]);
            cp16(so + 3 * ARRW * 4, (const void*)&Bl[(size_t)(bn + r) * D_MODEL + lc]);
        }
        asm volatile("cp.async.commit_group;");
    }

    for (int ch = 0; ch < D_MODEL / 32; ch++) {
        if (ch < D_MODEL / 32 - 1) {
            int nk = (ch + 1) * 32;
            uint32_t st = (uint32_t)(((ch + 1) & 1) * STGW * 4);
            #pragma unroll
            for (int t = 0; t < 2; t++) {
                int r = lr + t * 64;
                uint32_t so = s_b + st + (uint32_t)((r * GLDW + lw) * 4);
                cp16(so,                (const void*)&Ah[(size_t)(bm + r) * D_MODEL + nk + lc]);
                cp16(so + ARRW * 4,     (const void*)&Al[(size_t)(bm + r) * D_MODEL + nk + lc]);
                cp16(so + 2 * ARRW * 4, (const void*)&Bh[(size_t)(bn + r) * D_MODEL + nk + lc]);
                cp16(so + 3 * ARRW * 4, (const void*)&Bl[(size_t)(bn + r) * D_MODEL + nk + lc]);
            }
            asm volatile("cp.async.commit_group;");
            asm volatile("cp.async.wait_group 1;");
        } else {
            asm volatile("cp.async.wait_group 0;");
        }
        __syncthreads();

        const uint32_t aH = s_b + (uint32_t)((ch & 1) * STGW * 4);
        const uint32_t aL = aH + ARRW * 4;
        const uint32_t bH = aH + 2 * ARRW * 4;
        const uint32_t bL = aH + 3 * ARRW * 4;

        #pragma unroll
        for (int ks = 0; ks < 2; ks++) {
            uint32_t ah[4][4], al[4][4];
            #pragma unroll
            for (int mi = 0; mi < 4; mi++) {
                uint32_t ao = a_off + (uint32_t)((mi * 16 * GLDW + ks * 8) * 4);
                ldsm_x4(ah[mi], aH + ao);
                ldsm_x4(al[mi], aL + ao);
            }
            #pragma unroll
            for (int j2 = 0; j2 < 2; j2++) {
                uint32_t bh[4], bl[4];
                uint32_t bo = b_off + (uint32_t)((j2 * 16 * GLDW + ks * 8) * 4);
                ldsm_x4(bh, bH + bo);
                ldsm_x4(bl, bL + bo);
                #pragma unroll
                for (int mi = 0; mi < 4; mi++) {
                    float* c0 = c[mi][2 * j2];
                    float* c1 = c[mi][2 * j2 + 1];
                    mma_bf16(c0, ah[mi][0], ah[mi][1], ah[mi][2], ah[mi][3], bh[0], bh[1]);
                    mma_bf16(c0, ah[mi][0], ah[mi][1], ah[mi][2], ah[mi][3], bl[0], bl[1]);
                    mma_bf16(c0, al[mi][0], al[mi][1], al[mi][2], al[mi][3], bh[0], bh[1]);
                    mma_bf16(c1, ah[mi][0], ah[mi][1], ah[mi][2], ah[mi][3], bh[2], bh[3]);
                    mma_bf16(c1, ah[mi][0], ah[mi][1], ah[mi][2], ah[mi][3], bl[2], bl[3]);
                    mma_bf16(c1, al[mi][0], al[mi][1], al[mi][2], al[mi][3], bh[2], bh[3]);
                }
            }
        }
        __syncthreads();
    }

    #pragma unroll
    for (int mi = 0; mi < 4; mi++) {
        int r0 = bm + wm * 64 + mi * 16 + g, r1 = r0 + 8;
        #pragma unroll
        for (int nj = 0; nj < 4; nj++) {
            int col = bn + wn * 32 + nj * 8 + 2 * q4;
            float2 bb = *(const float2*)&bias[col];
            float v00 = (c[mi][nj][0] + bb.x) * scale, v01 = (c[mi][nj][1] + bb.y) * scale;
            float v10 = (c[mi][nj][2] + bb.x) * scale, v11 = (c[mi][nj][3] + bb.y) * scale;
            if (mode == 0) {
                *(float2*)&((float*)out)[(size_t)r0 * D_MODEL + col] = make_float2(v00, v01);
                *(float2*)&((float*)out)[(size_t)r1 * D_MODEL + col] = make_float2(v10, v11);
            } else {
                *(__half2*)&((__half*)out)[(size_t)r0 * D_MODEL + col] = __floats2half2_rn(v00, v01);
                *(__half2*)&((__half*)out)[(size_t)r1 * D_MODEL + col] = __floats2half2_rn(v10, v11);
            }
        }
    }
}

// ---------------------------------------------------------------------------
// Flash attention, fp16 m16n8k16, exp2-domain softmax.
// Grid (SEQ/128, NHEADS, NBATCH), 256 threads (8 warps x 16 q-rows).
// V kept in natural [kv][hd] layout; P@V B-fragments via ldmatrix.x4.trans.
// ---------------------------------------------------------------------------
__global__ __launch_bounds__(256)
void flash_attn_f16(const __half* __restrict__ Qh, const __half* __restrict__ Kh,
                    const __half* __restrict__ Vh,
                    __nv_bfloat16* __restrict__ AOh, __nv_bfloat16* __restrict__ AOl) {
    __shared__ __half Ks[64 * 72];
    __shared__ __half Vs[64 * 72];

    const int tid  = threadIdx.x;
    const int lane = tid & 31;
    const int w    = tid >> 5;
    const int g    = lane >> 2;
    const int q4   = lane & 3;

    const int qblk = blockIdx.x;
    const int h    = blockIdx.y;
    const int n    = blockIdx.z;
    const int rowbase = n * SEQ + qblk * 128;
    const int col0    = h * HDIM;

    const uint32_t ks_b = (uint32_t)__cvta_generic_to_shared(Ks);
    const uint32_t vs_b = (uint32_t)__cvta_generic_to_shared(Vs);
    const int lm_row = ((lane >> 4) << 3) | (lane & 7);
    const uint32_t k_off = (uint32_t)((lm_row * 72 + (((lane >> 3) & 1) << 3)) * 2);
    const uint32_t v_off = (uint32_t)(((lane & 15) * 72 + (lane >> 4) * 8) * 2);

    // Q fragments (4 k-steps), one-time gmem load
    uint32_t qf[4][4];
    const int qr0 = rowbase + w * 16 + g, qr1 = qr0 + 8;
    #pragma unroll
    for (int ks = 0; ks < 4; ks++) {
        int cb = col0 + ks * 16 + 2 * q4;
        qf[ks][0] = *(const uint32_t*)&Qh[(size_t)qr0 * D_MODEL + cb];
        qf[ks][1] = *(const uint32_t*)&Qh[(size_t)qr1 * D_MODEL + cb];
        qf[ks][2] = *(const uint32_t*)&Qh[(size_t)qr0 * D_MODEL + cb + 8];
        qf[ks][3] = *(const uint32_t*)&Qh[(size_t)qr1 * D_MODEL + cb + 8];
    }

    float oc[8][4] = {};
    float m0 = -1e30f, m1 = -1e30f, l0 = 0.0f, l1 = 0.0f;

    for (int s0 = 0; s0 < SEQ; s0 += 64) {
        #pragma unroll
        for (int t = 0; t < 2; t++) {
            int idx = tid + t * 256;          // 0..511
            int r = idx >> 3, c8 = (idx & 7) * 8;
            size_t goff = (size_t)(n * SEQ + s0 + r) * D_MODEL + col0 + c8;
            *(uint4*)&Ks[r * 72 + c8] = *(const uint4*)&Kh[goff];
            *(uint4*)&Vs[r * 72 + c8] = *(const uint4*)&Vh[goff];
        }
        __syncthreads();

        // S = Qs @ K^T
        float sc[8][4];
        #pragma unroll
        for (int j = 0; j < 8; j++) { sc[j][0] = sc[j][1] = sc[j][2] = sc[j][3] = 0.0f; }
        #pragma unroll
        for (int ks = 0; ks < 4; ks++) {
            #pragma unroll
            for (int j2 = 0; j2 < 4; j2++) {
                uint32_t b[4];
                ldsm_x4(b, ks_b + k_off + (uint32_t)(j2 * 2304 + ks * 32));
                mma_f16(sc[2 * j2],     qf[ks][0], qf[ks][1], qf[ks][2], qf[ks][3], b[0], b[1]);
                mma_f16(sc[2 * j2 + 1], qf[ks][0], qf[ks][1], qf[ks][2], qf[ks][3], b[2], b[3]);
            }
        }

        // online softmax (rows g, g+8)
        float rm0 = -1e30f, rm1 = -1e30f;
        #pragma unroll
        for (int j = 0; j < 8; j++) {
            rm0 = fmaxf(rm0, fmaxf(sc[j][0], sc[j][1]));
            rm1 = fmaxf(rm1, fmaxf(sc[j][2], sc[j][3]));
        }
        rm0 = fmaxf(rm0, __shfl_xor_sync(0xffffffffu, rm0, 1));
        rm0 = fmaxf(rm0, __shfl_xor_sync(0xffffffffu, rm0, 2));
        rm1 = fmaxf(rm1, __shfl_xor_sync(0xffffffffu, rm1, 1));
        rm1 = fmaxf(rm1, __shfl_xor_sync(0xffffffffu, rm1, 2));
        float m0n = fmaxf(m0, rm0), m1n = fmaxf(m1, rm1);
        float corr0 = fast_ex2(m0 - m0n), corr1 = fast_ex2(m1 - m1n);
        m0 = m0n; m1 = m1n;

        float rs0 = 0.0f, rs1 = 0.0f;
        #pragma unroll
        for (int j = 0; j < 8; j++) {
            sc[j][0] = fast_ex2(sc[j][0] - m0);
            sc[j][1] = fast_ex2(sc[j][1] - m0);
            sc[j][2] = fast_ex2(sc[j][2] - m1);
            sc[j][3] = fast_ex2(sc[j][3] - m1);
            rs0 += sc[j][0] + sc[j][1];
            rs1 += sc[j][2] + sc[j][3];
            oc[j][0] *= corr0; oc[j][1] *= corr0;
            oc[j][2] *= corr1; oc[j][3] *= corr1;
        }
        rs0 += __shfl_xor_sync(0xffffffffu, rs0, 1);
        rs0 += __shfl_xor_sync(0xffffffffu, rs0, 2);
        rs1 += __shfl_xor_sync(0xffffffffu, rs1, 1);
        rs1 += __shfl_xor_sync(0xffffffffu, rs1, 2);
        l0 = l0 * corr0 + rs0;
        l1 = l1 * corr1 + rs1;

        // O += P @ V : B-frags from natural-layout V via ldmatrix.trans
        #pragma unroll
        for (int ks = 0; ks < 4; ks++) {
            uint32_t pa0 = hpack(sc[2 * ks][0],     sc[2 * ks][1]);
            uint32_t pa1 = hpack(sc[2 * ks][2],     sc[2 * ks][3]);
            uint32_t pa2 = hpack(sc[2 * ks + 1][0], sc[2 * ks + 1][1]);
            uint32_t pa3 = hpack(sc[2 * ks + 1][2], sc[2 * ks + 1][3]);
            #pragma unroll
            for (int j2 = 0; j2 < 4; j2++) {
                uint32_t b[4];
                // row = ks*16 + (lane&15) [kv], col = j2*16 + (lane>>4)*8 [hd]
                ldsm_x4_t(b, vs_b + v_off + (uint32_t)((ks * 16 * 72 + j2 * 16) * 2));
                mma_f16(oc[2 * j2],     pa0, pa1, pa2, pa3, b[0], b[1]);
                mma_f16(oc[2 * j2 + 1], pa0, pa1, pa2, pa3, b[2], b[3]);
            }
        }
        __syncthreads();
    }

    // normalize + bf16 hi/lo store
    float il0 = 1.0f / l0, il1 = 1.0f / l1;
    const size_t or0 = (size_t)qr0 * D_MODEL + col0;
    const size_t or1 = (size_t)qr1 * D_MODEL + col0;
    #pragma unroll
    for (int j = 0; j < 8; j++) {
        int c = j * 8 + 2 * q4;
        float v00 = oc[j][0] * il0, v01 = oc[j][1] * il0;
        float v10 = oc[j][2] * il1, v11 = oc[j][3] * il1;
        __nv_bfloat162 h0 = __floats2bfloat162_rn(v00, v01);
        __nv_bfloat162 h1 = __floats2bfloat162_rn(v10, v11);
        *(__nv_bfloat162*)&AOh[or0 + c] = h0;
        *(__nv_bfloat162*)&AOh[or1 + c] = h1;
        *(__nv_bfloat162*)&AOl[or0 + c] =
            __floats2bfloat162_rn(v00 - __bfloat162float(h0.x), v01 - __bfloat162float(h0.y));
        *(__nv_bfloat162*)&AOl[or1 + c] =
            __floats2bfloat162_rn(v10 - __bfloat162float(h1.x), v11 - __bfloat162float(h1.y));
    }
}

// ---------------------------------------------------------------------------

extern "C" void kernel_launch(void* const* d_in, const int* in_sizes, int n_in,
                              void* d_out, int out_size) {
    const float* query = (const float*)d_in[0];
    const float* key   = (const float*)d_in[1];
    const float* value = (const float*)d_in[2];
    const float* Wq    = (const float*)d_in[3];
    const float* bq    = (const float*)d_in[4];
    const float* Wk    = (const float*)d_in[5];
    const float* bk    = (const float*)d_in[6];
    const float* Wv    = (const float*)d_in[7];
    const float* bv    = (const float*)d_in[8];
    const float* Wo    = (const float*)d_in[9];
    const float* bo    = (const float*)d_in[10];
    float* out = (float*)d_out;

    __nv_bfloat16 *qh, *ql, *kh, *kl, *vh, *vl;
    __nv_bfloat16 *wqh, *wql, *wkh, *wkl, *wvh, *wvl, *woh, *wol;
    __nv_bfloat16 *aoh, *aol;
    __half *Qh, *Kh, *Vh;
    cudaGetSymbolAddress((void**)&qh, g_qh);   cudaGetSymbolAddress((void**)&ql, g_ql);
    cudaGetSymbolAddress((void**)&kh, g_kh);   cudaGetSymbolAddress((void**)&kl, g_kl);
    cudaGetSymbolAddress((void**)&vh, g_vh);   cudaGetSymbolAddress((void**)&vl, g_vl);
    cudaGetSymbolAddress((void**)&wqh, g_Wqh); cudaGetSymbolAddress((void**)&wql, g_Wql);
    cudaGetSymbolAddress((void**)&wkh, g_Wkh); cudaGetSymbolAddress((void**)&wkl, g_Wkl);
    cudaGetSymbolAddress((void**)&wvh, g_Wvh); cudaGetSymbolAddress((void**)&wvl, g_Wvl);
    cudaGetSymbolAddress((void**)&woh, g_Woh); cudaGetSymbolAddress((void**)&wol, g_Wol);
    cudaGetSymbolAddress((void**)&aoh, g_AOh); cudaGetSymbolAddress((void**)&aol, g_AOl);
    cudaGetSymbolAddress((void**)&Qh, g_Qh);
    cudaGetSymbolAddress((void**)&Kh, g_Kh);
    cudaGetSymbolAddress((void**)&Vh, g_Vh);

    const int n4_in = MROWS * D_MODEL / 4;
    const int n4_w  = D_MODEL * D_MODEL / 4;
    cvt_split<<<n4_in / 256, 256>>>(query, qh, ql, n4_in);
    cvt_split<<<n4_in / 256, 256>>>(key,   kh, kl, n4_in);
    cvt_split<<<n4_in / 256, 256>>>(value, vh, vl, n4_in);
    cvt_split<<<n4_w / 256, 256>>>(Wq, wqh, wql, n4_w);
    cvt_split<<<n4_w / 256, 256>>>(Wk, wkh, wkl, n4_w);
    cvt_split<<<n4_w / 256, 256>>>(Wv, wvh, wvl, n4_w);
    cvt_split<<<n4_w / 256, 256>>>(Wo, woh, wol, n4_w);

    cudaFuncSetAttribute(gemm_bf16split2,
                         cudaFuncAttributeMaxDynamicSharedMemorySize, GSMEM_BYTES);
    dim3 ggrid(MROWS / 128, D_MODEL / 128);
    gemm_bf16split2<<<ggrid, 256, GSMEM_BYTES>>>(qh, ql, wqh, wql, bq, Qh, 1, 0.125f * LOG2E);
    gemm_bf16split2<<<ggrid, 256, GSMEM_BYTES>>>(kh, kl, wkh, wkl, bk, Kh, 1, 1.0f);
    gemm_bf16split2<<<ggrid, 256, GSMEM_BYTES>>>(vh, vl, wvh, wvl, bv, Vh, 1, 1.0f);

    dim3 fgrid(SEQ / 128, NHEADS, NBATCH);
    flash_attn_f16<<<fgrid, 256>>>(Qh, Kh, Vh, aoh, aol);

    gemm_bf16split2<<<ggrid, 256, GSMEM_BYTES>>>(aoh, aol, woh, wol, bo, out, 0, 1.0f);
}

// round 9
// speedup vs baseline: 11.8494x; 1.0873x over previous
#include <cuda_runtime.h>
#include <cuda_fp16.h>
#include <cuda_bf16.h>
#include <math.h>
#include <stdint.h>

#define D_MODEL 512
#define NBATCH  2
#define SEQ     4096
#define NHEADS  8
#define HDIM    64
#define MROWS   (NBATCH * SEQ)   // 8192
#define LOG2E   1.44269504088896f

// ---- scratch -------------------------------------------------------------
__device__ __nv_bfloat16 g_qh[MROWS * D_MODEL], g_ql[MROWS * D_MODEL];
__device__ __nv_bfloat16 g_kh[MROWS * D_MODEL], g_kl[MROWS * D_MODEL];
__device__ __nv_bfloat16 g_vh[MROWS * D_MODEL], g_vl[MROWS * D_MODEL];
__device__ __nv_bfloat16 g_Wqh[D_MODEL * D_MODEL], g_Wql[D_MODEL * D_MODEL];
__device__ __nv_bfloat16 g_Wkh[D_MODEL * D_MODEL], g_Wkl[D_MODEL * D_MODEL];
__device__ __nv_bfloat16 g_Wvh[D_MODEL * D_MODEL], g_Wvl[D_MODEL * D_MODEL];
__device__ __nv_bfloat16 g_Woh[D_MODEL * D_MODEL], g_Wol[D_MODEL * D_MODEL];
__device__ __half g_Qh[MROWS * D_MODEL];
__device__ __half g_Kh[MROWS * D_MODEL];
__device__ __half g_Vh[MROWS * D_MODEL];
__device__ __nv_bfloat16 g_AOh[MROWS * D_MODEL], g_AOl[MROWS * D_MODEL];

// ---- helpers -------------------------------------------------------------
__device__ __forceinline__ float fast_ex2(float x) {
    float y;
    asm("ex2.approx.f32 %0, %1;" : "=f"(y) : "f"(x));
    return y;
}
__device__ __forceinline__ uint32_t hpack(float x, float y) {
    __half2 h = __floats2half2_rn(x, y);
    return *(uint32_t*)&h;
}
__device__ __forceinline__ void mma_f16(float c[4],
                                        uint32_t a0, uint32_t a1, uint32_t a2, uint32_t a3,
                                        uint32_t b0, uint32_t b1) {
    asm volatile(
        "mma.sync.aligned.m16n8k16.row.col.f32.f16.f16.f32 "
        "{%0,%1,%2,%3}, {%4,%5,%6,%7}, {%8,%9}, {%0,%1,%2,%3};\n"
        : "+f"(c[0]), "+f"(c[1]), "+f"(c[2]), "+f"(c[3])
        : "r"(a0), "r"(a1), "r"(a2), "r"(a3), "r"(b0), "r"(b1));
}
__device__ __forceinline__ void mma_bf16(float c[4],
                                         uint32_t a0, uint32_t a1, uint32_t a2, uint32_t a3,
                                         uint32_t b0, uint32_t b1) {
    asm volatile(
        "mma.sync.aligned.m16n8k16.row.col.f32.bf16.bf16.f32 "
        "{%0,%1,%2,%3}, {%4,%5,%6,%7}, {%8,%9}, {%0,%1,%2,%3};\n"
        : "+f"(c[0]), "+f"(c[1]), "+f"(c[2]), "+f"(c[3])
        : "r"(a0), "r"(a1), "r"(a2), "r"(a3), "r"(b0), "r"(b1));
}
__device__ __forceinline__ void ldsm_x4(uint32_t r[4], uint32_t saddr) {
    asm volatile("ldmatrix.sync.aligned.m8n8.x4.shared.b16 {%0,%1,%2,%3}, [%4];"
                 : "=r"(r[0]), "=r"(r[1]), "=r"(r[2]), "=r"(r[3]) : "r"(saddr));
}
__device__ __forceinline__ void ldsm_x4_t(uint32_t r[4], uint32_t saddr) {
    asm volatile("ldmatrix.sync.aligned.m8n8.x4.trans.shared.b16 {%0,%1,%2,%3}, [%4];"
                 : "=r"(r[0]), "=r"(r[1]), "=r"(r[2]), "=r"(r[3]) : "r"(saddr));
}
__device__ __forceinline__ void cp16(uint32_t saddr, const void* gaddr) {
    asm volatile("cp.async.cg.shared.global [%0], [%1], 16;" :: "r"(saddr), "l"(gaddr));
}

// ---------------------------------------------------------------------------
// Fused fp32 -> bf16 hi/lo split for all 7 tensors (one launch).
// Tensors 0..2: MROWS*D_MODEL elements; 3..6: D_MODEL*D_MODEL.
// ---------------------------------------------------------------------------
struct CvtArgs {
    const float*   src[7];
    __nv_bfloat16* hi[7];
    __nv_bfloat16* lo[7];
};
#define CVT_BIG_BLOCKS   (MROWS * D_MODEL / 4 / 256)     // 4096
#define CVT_SMALL_BLOCKS (D_MODEL * D_MODEL / 4 / 256)   // 256
#define CVT_TOTAL_BLOCKS (3 * CVT_BIG_BLOCKS + 4 * CVT_SMALL_BLOCKS)  // 13312

__global__ __launch_bounds__(256)
void cvt_split_all(CvtArgs args) {
    int b = blockIdx.x;
    int t, base;
    if (b < 3 * CVT_BIG_BLOCKS) {
        t = b / CVT_BIG_BLOCKS;
        base = b % CVT_BIG_BLOCKS;
    } else {
        int bb = b - 3 * CVT_BIG_BLOCKS;
        t = 3 + bb / CVT_SMALL_BLOCKS;
        base = bb % CVT_SMALL_BLOCKS;
    }
    int i = base * 256 + threadIdx.x;
    float4 v = ((const float4*)args.src[t])[i];
    __nv_bfloat162 h0 = __floats2bfloat162_rn(v.x, v.y);
    __nv_bfloat162 h1 = __floats2bfloat162_rn(v.z, v.w);
    ((__nv_bfloat162*)args.hi[t])[2 * i]     = h0;
    ((__nv_bfloat162*)args.hi[t])[2 * i + 1] = h1;
    ((__nv_bfloat162*)args.lo[t])[2 * i] = __floats2bfloat162_rn(
        v.x - __bfloat162float(h0.x), v.y - __bfloat162float(h0.y));
    ((__nv_bfloat162*)args.lo[t])[2 * i + 1] = __floats2bfloat162_rn(
        v.z - __bfloat162float(h1.x), v.w - __bfloat162float(h1.y));
}

// ---------------------------------------------------------------------------
// Split-bf16 GEMM, 128x128 tile, 256 threads, double-buffered cp.async with
// ONE __syncthreads per k-chunk (cp for next stage issued after the barrier).
// C[m,n] = sum_k A[m,k]*B[n,k] + bias[n]; 3-term: ah*bh + ah*bl + al*bh.
// mode 0: fp32 out.  mode 1: fp16 out, scaled.
// ---------------------------------------------------------------------------
#define GLDW 20
#define ARRW (128 * GLDW)          // words per array   = 2560
#define STGW (4 * ARRW)            // words per stage   = 10240
#define GSMEM_BYTES (2 * STGW * 4) // 81920

__global__ __launch_bounds__(256, 1)
void gemm_bf16split2(const __nv_bfloat16* __restrict__ Ah, const __nv_bfloat16* __restrict__ Al,
                     const __nv_bfloat16* __restrict__ Bh, const __nv_bfloat16* __restrict__ Bl,
                     const float* __restrict__ bias, void* __restrict__ out,
                     int mode, float scale) {
    extern __shared__ uint32_t sg[];

    const int tid  = threadIdx.x;
    const int lane = tid & 31;
    const int w    = tid >> 5;
    const int wm   = w >> 2;        // 0..1
    const int wn   = w & 3;         // 0..3
    const int g    = lane >> 2;
    const int q4   = lane & 3;
    const int bm   = blockIdx.x * 128;
    const int bn   = blockIdx.y * 128;

    const uint32_t s_b = (uint32_t)__cvta_generic_to_shared(sg);

    const uint32_t a_off = (uint32_t)(((wm * 64 + (lane & 15)) * GLDW + (lane >> 4) * 4) * 4);
    const int lm_row = ((lane >> 4) << 3) | (lane & 7);
    const uint32_t b_off = (uint32_t)(((wn * 32 + lm_row) * GLDW + ((lane >> 3) & 1) * 4) * 4);

    const int lr = tid >> 2;               // 0..63
    const int lw = (tid & 3) * 4;          // word col
    const int lc = (tid & 3) * 8;          // bf16 col

    float c[4][4][4] = {};

    // prologue: chunk 0 -> stage 0
    #pragma unroll
    for (int t = 0; t < 2; t++) {
        int r = lr + t * 64;
        uint32_t so = s_b + (uint32_t)((r * GLDW + lw) * 4);
        cp16(so,                (const void*)&Ah[(size_t)(bm + r) * D_MODEL + lc]);
        cp16(so + ARRW * 4,     (const void*)&Al[(size_t)(bm + r) * D_MODEL + lc]);
        cp16(so + 2 * ARRW * 4, (const void*)&Bh[(size_t)(bn + r) * D_MODEL + lc]);
        cp16(so + 3 * ARRW * 4, (const void*)&Bl[(size_t)(bn + r) * D_MODEL + lc]);
    }
    asm volatile("cp.async.commit_group;");

    for (int ch = 0; ch < D_MODEL / 32; ch++) {
        asm volatile("cp.async.wait_group 0;");
        __syncthreads();   // stage ch&1 ready; stage (ch+1)&1 readers (iter ch-1) retired

        if (ch < D_MODEL / 32 - 1) {
            int nk = (ch + 1) * 32;
            uint32_t st = (uint32_t)(((ch + 1) & 1) * STGW * 4);
            #pragma unroll
            for (int t = 0; t < 2; t++) {
                int r = lr + t * 64;
                uint32_t so = s_b + st + (uint32_t)((r * GLDW + lw) * 4);
                cp16(so,                (const void*)&Ah[(size_t)(bm + r) * D_MODEL + nk + lc]);
                cp16(so + ARRW * 4,     (const void*)&Al[(size_t)(bm + r) * D_MODEL + nk + lc]);
                cp16(so + 2 * ARRW * 4, (const void*)&Bh[(size_t)(bn + r) * D_MODEL + nk + lc]);
                cp16(so + 3 * ARRW * 4, (const void*)&Bl[(size_t)(bn + r) * D_MODEL + nk + lc]);
            }
            asm volatile("cp.async.commit_group;");
        }

        const uint32_t aH = s_b + (uint32_t)((ch & 1) * STGW * 4);
        const uint32_t aL = aH + ARRW * 4;
        const uint32_t bH = aH + 2 * ARRW * 4;
        const uint32_t bL = aH + 3 * ARRW * 4;

        #pragma unroll
        for (int ks = 0; ks < 2; ks++) {
            uint32_t ah[4][4], al[4][4];
            #pragma unroll
            for (int mi = 0; mi < 4; mi++) {
                uint32_t ao = a_off + (uint32_t)((mi * 16 * GLDW + ks * 8) * 4);
                ldsm_x4(ah[mi], aH + ao);
                ldsm_x4(al[mi], aL + ao);
            }
            #pragma unroll
            for (int j2 = 0; j2 < 2; j2++) {
                uint32_t bh[4], bl[4];
                uint32_t bo = b_off + (uint32_t)((j2 * 16 * GLDW + ks * 8) * 4);
                ldsm_x4(bh, bH + bo);
                ldsm_x4(bl, bL + bo);
                #pragma unroll
                for (int mi = 0; mi < 4; mi++) {
                    float* c0 = c[mi][2 * j2];
                    float* c1 = c[mi][2 * j2 + 1];
                    mma_bf16(c0, ah[mi][0], ah[mi][1], ah[mi][2], ah[mi][3], bh[0], bh[1]);
                    mma_bf16(c0, ah[mi][0], ah[mi][1], ah[mi][2], ah[mi][3], bl[0], bl[1]);
                    mma_bf16(c0, al[mi][0], al[mi][1], al[mi][2], al[mi][3], bh[0], bh[1]);
                    mma_bf16(c1, ah[mi][0], ah[mi][1], ah[mi][2], ah[mi][3], bh[2], bh[3]);
                    mma_bf16(c1, ah[mi][0], ah[mi][1], ah[mi][2], ah[mi][3], bl[2], bl[3]);
                    mma_bf16(c1, al[mi][0], al[mi][1], al[mi][2], al[mi][3], bh[2], bh[3]);
                }
            }
        }
        // no bottom sync: next iteration's barrier protects stage reuse
    }

    #pragma unroll
    for (int mi = 0; mi < 4; mi++) {
        int r0 = bm + wm * 64 + mi * 16 + g, r1 = r0 + 8;
        #pragma unroll
        for (int nj = 0; nj < 4; nj++) {
            int col = bn + wn * 32 + nj * 8 + 2 * q4;
            float2 bb = *(const float2*)&bias[col];
            float v00 = (c[mi][nj][0] + bb.x) * scale, v01 = (c[mi][nj][1] + bb.y) * scale;
            float v10 = (c[mi][nj][2] + bb.x) * scale, v11 = (c[mi][nj][3] + bb.y) * scale;
            if (mode == 0) {
                *(float2*)&((float*)out)[(size_t)r0 * D_MODEL + col] = make_float2(v00, v01);
                *(float2*)&((float*)out)[(size_t)r1 * D_MODEL + col] = make_float2(v10, v11);
            } else {
                *(__half2*)&((__half*)out)[(size_t)r0 * D_MODEL + col] = __floats2half2_rn(v00, v01);
                *(__half2*)&((__half*)out)[(size_t)r1 * D_MODEL + col] = __floats2half2_rn(v10, v11);
            }
        }
    }
}

// ---------------------------------------------------------------------------
// Flash attention, fp16 m16n8k16, exp2-domain softmax, register-staged
// K/V prefetch (LDG for chunk i+1 issued before chunk i's mma work).
// Grid (SEQ/128, NHEADS, NBATCH), 256 threads (8 warps x 16 q-rows).
// ---------------------------------------------------------------------------
__global__ __launch_bounds__(256, 2)
void flash_attn_f16(const __half* __restrict__ Qh, const __half* __restrict__ Kh,
                    const __half* __restrict__ Vh,
                    __nv_bfloat16* __restrict__ AOh, __nv_bfloat16* __restrict__ AOl) {
    __shared__ __half Ks[64 * 72];
    __shared__ __half Vs[64 * 72];

    const int tid  = threadIdx.x;
    const int lane = tid & 31;
    const int w    = tid >> 5;
    const int g    = lane >> 2;
    const int q4   = lane & 3;

    const int qblk = blockIdx.x;
    const int h    = blockIdx.y;
    const int n    = blockIdx.z;
    const int rowbase = n * SEQ + qblk * 128;
    const int col0    = h * HDIM;

    const uint32_t ks_b = (uint32_t)__cvta_generic_to_shared(Ks);
    const uint32_t vs_b = (uint32_t)__cvta_generic_to_shared(Vs);
    const int lm_row = ((lane >> 4) << 3) | (lane & 7);
    const uint32_t k_off = (uint32_t)((lm_row * 72 + (((lane >> 3) & 1) << 3)) * 2);
    const uint32_t v_off = (uint32_t)(((lane & 15) * 72 + (lane >> 4) * 8) * 2);

    // chunk-load geometry (two rows per thread)
    const int cr0 = tid >> 3,        cc0 = (tid & 7) * 8;           // idx = tid
    const int cr1 = (tid + 256) >> 3, cc1 = (tid & 7) * 8;          // idx = tid+256

    // Q fragments (4 k-steps), one-time gmem load
    uint32_t qf[4][4];
    const int qr0 = rowbase + w * 16 + g, qr1 = qr0 + 8;
    #pragma unroll
    for (int ks = 0; ks < 4; ks++) {
        int cb = col0 + ks * 16 + 2 * q4;
        qf[ks][0] = *(const uint32_t*)&Qh[(size_t)qr0 * D_MODEL + cb];
        qf[ks][1] = *(const uint32_t*)&Qh[(size_t)qr1 * D_MODEL + cb];
        qf[ks][2] = *(const uint32_t*)&Qh[(size_t)qr0 * D_MODEL + cb + 8];
        qf[ks][3] = *(const uint32_t*)&Qh[(size_t)qr1 * D_MODEL + cb + 8];
    }

    // prefetch chunk 0 into registers
    uint4 kr0, kr1, vr0, vr1;
    {
        size_t g0 = (size_t)(n * SEQ + cr0) * D_MODEL + col0 + cc0;
        size_t g1 = (size_t)(n * SEQ + cr1) * D_MODEL + col0 + cc1;
        kr0 = *(const uint4*)&Kh[g0]; vr0 = *(const uint4*)&Vh[g0];
        kr1 = *(const uint4*)&Kh[g1]; vr1 = *(const uint4*)&Vh[g1];
    }

    float oc[8][4] = {};
    float m0 = -1e30f, m1 = -1e30f, l0 = 0.0f, l1 = 0.0f;

    for (int s0 = 0; s0 < SEQ; s0 += 64) {
        __syncthreads();   // prior chunk's smem readers retired
        *(uint4*)&Ks[cr0 * 72 + cc0] = kr0;
        *(uint4*)&Vs[cr0 * 72 + cc0] = vr0;
        *(uint4*)&Ks[cr1 * 72 + cc1] = kr1;
        *(uint4*)&Vs[cr1 * 72 + cc1] = vr1;
        __syncthreads();

        if (s0 + 64 < SEQ) {   // prefetch next chunk; consumed next iteration
            size_t g0 = (size_t)(n * SEQ + s0 + 64 + cr0) * D_MODEL + col0 + cc0;
            size_t g1 = (size_t)(n * SEQ + s0 + 64 + cr1) * D_MODEL + col0 + cc1;
            kr0 = *(const uint4*)&Kh[g0]; vr0 = *(const uint4*)&Vh[g0];
            kr1 = *(const uint4*)&Kh[g1]; vr1 = *(const uint4*)&Vh[g1];
        }

        // S = Qs @ K^T
        float sc[8][4];
        #pragma unroll
        for (int j = 0; j < 8; j++) { sc[j][0] = sc[j][1] = sc[j][2] = sc[j][3] = 0.0f; }
        #pragma unroll
        for (int ks = 0; ks < 4; ks++) {
            #pragma unroll
            for (int j2 = 0; j2 < 4; j2++) {
                uint32_t b[4];
                ldsm_x4(b, ks_b + k_off + (uint32_t)(j2 * 2304 + ks * 32));
                mma_f16(sc[2 * j2],     qf[ks][0], qf[ks][1], qf[ks][2], qf[ks][3], b[0], b[1]);
                mma_f16(sc[2 * j2 + 1], qf[ks][0], qf[ks][1], qf[ks][2], qf[ks][3], b[2], b[3]);
            }
        }

        // online softmax (rows g, g+8)
        float rm0 = -1e30f, rm1 = -1e30f;
        #pragma unroll
        for (int j = 0; j < 8; j++) {
            rm0 = fmaxf(rm0, fmaxf(sc[j][0], sc[j][1]));
            rm1 = fmaxf(rm1, fmaxf(sc[j][2], sc[j][3]));
        }
        rm0 = fmaxf(rm0, __shfl_xor_sync(0xffffffffu, rm0, 1));
        rm0 = fmaxf(rm0, __shfl_xor_sync(0xffffffffu, rm0, 2));
        rm1 = fmaxf(rm1, __shfl_xor_sync(0xffffffffu, rm1, 1));
        rm1 = fmaxf(rm1, __shfl_xor_sync(0xffffffffu, rm1, 2));
        float m0n = fmaxf(m0, rm0), m1n = fmaxf(m1, rm1);
        float corr0 = fast_ex2(m0 - m0n), corr1 = fast_ex2(m1 - m1n);
        m0 = m0n; m1 = m1n;

        float rs0 = 0.0f, rs1 = 0.0f;
        #pragma unroll
        for (int j = 0; j < 8; j++) {
            sc[j][0] = fast_ex2(sc[j][0] - m0);
            sc[j][1] = fast_ex2(sc[j][1] - m0);
            sc[j][2] = fast_ex2(sc[j][2] - m1);
            sc[j][3] = fast_ex2(sc[j][3] - m1);
            rs0 += sc[j][0] + sc[j][1];
            rs1 += sc[j][2] + sc[j][3];
            oc[j][0] *= corr0; oc[j][1] *= corr0;
            oc[j][2] *= corr1; oc[j][3] *= corr1;
        }
        rs0 += __shfl_xor_sync(0xffffffffu, rs0, 1);
        rs0 += __shfl_xor_sync(0xffffffffu, rs0, 2);
        rs1 += __shfl_xor_sync(0xffffffffu, rs1, 1);
        rs1 += __shfl_xor_sync(0xffffffffu, rs1, 2);
        l0 = l0 * corr0 + rs0;
        l1 = l1 * corr1 + rs1;

        // O += P @ V : B-frags from natural-layout V via ldmatrix.trans
        #pragma unroll
        for (int ks = 0; ks < 4; ks++) {
            uint32_t pa0 = hpack(sc[2 * ks][0],     sc[2 * ks][1]);
            uint32_t pa1 = hpack(sc[2 * ks][2],     sc[2 * ks][3]);
            uint32_t pa2 = hpack(sc[2 * ks + 1][0], sc[2 * ks + 1][1]);
            uint32_t pa3 = hpack(sc[2 * ks + 1][2], sc[2 * ks + 1][3]);
            #pragma unroll
            for (int j2 = 0; j2 < 4; j2++) {
                uint32_t b[4];
                ldsm_x4_t(b, vs_b + v_off + (uint32_t)((ks * 16 * 72 + j2 * 16) * 2));
                mma_f16(oc[2 * j2],     pa0, pa1, pa2, pa3, b[0], b[1]);
                mma_f16(oc[2 * j2 + 1], pa0, pa1, pa2, pa3, b[2], b[3]);
            }
        }
    }

    // normalize + bf16 hi/lo store
    float il0 = 1.0f / l0, il1 = 1.0f / l1;
    const size_t or0 = (size_t)qr0 * D_MODEL + col0;
    const size_t or1 = (size_t)qr1 * D_MODEL + col0;
    #pragma unroll
    for (int j = 0; j < 8; j++) {
        int c = j * 8 + 2 * q4;
        float v00 = oc[j][0] * il0, v01 = oc[j][1] * il0;
        float v10 = oc[j][2] * il1, v11 = oc[j][3] * il1;
        __nv_bfloat162 h0 = __floats2bfloat162_rn(v00, v01);
        __nv_bfloat162 h1 = __floats2bfloat162_rn(v10, v11);
        *(__nv_bfloat162*)&AOh[or0 + c] = h0;
        *(__nv_bfloat162*)&AOh[or1 + c] = h1;
        *(__nv_bfloat162*)&AOl[or0 + c] =
            __floats2bfloat162_rn(v00 - __bfloat162float(h0.x), v01 - __bfloat162float(h0.y));
        *(__nv_bfloat162*)&AOl[or1 + c] =
            __floats2bfloat162_rn(v10 - __bfloat162float(h1.x), v11 - __bfloat162float(h1.y));
    }
}

// ---------------------------------------------------------------------------

extern "C" void kernel_launch(void* const* d_in, const int* in_sizes, int n_in,
                              void* d_out, int out_size) {
    const float* query = (const float*)d_in[0];
    const float* key   = (const float*)d_in[1];
    const float* value = (const float*)d_in[2];
    const float* Wq    = (const float*)d_in[3];
    const float* bq    = (const float*)d_in[4];
    const float* Wk    = (const float*)d_in[5];
    const float* bk    = (const float*)d_in[6];
    const float* Wv    = (const float*)d_in[7];
    const float* bv    = (const float*)d_in[8];
    const float* Wo    = (const float*)d_in[9];
    const float* bo    = (const float*)d_in[10];
    float* out = (float*)d_out;

    __nv_bfloat16 *qh, *ql, *kh, *kl, *vh, *vl;
    __nv_bfloat16 *wqh, *wql, *wkh, *wkl, *wvh, *wvl, *woh, *wol;
    __nv_bfloat16 *aoh, *aol;
    __half *Qh, *Kh, *Vh;
    cudaGetSymbolAddress((void**)&qh, g_qh);   cudaGetSymbolAddress((void**)&ql, g_ql);
    cudaGetSymbolAddress((void**)&kh, g_kh);   cudaGetSymbolAddress((void**)&kl, g_kl);
    cudaGetSymbolAddress((void**)&vh, g_vh);   cudaGetSymbolAddress((void**)&vl, g_vl);
    cudaGetSymbolAddress((void**)&wqh, g_Wqh); cudaGetSymbolAddress((void**)&wql, g_Wql);
    cudaGetSymbolAddress((void**)&wkh, g_Wkh); cudaGetSymbolAddress((void**)&wkl, g_Wkl);
    cudaGetSymbolAddress((void**)&wvh, g_Wvh); cudaGetSymbolAddress((void**)&wvl, g_Wvl);
    cudaGetSymbolAddress((void**)&woh, g_Woh); cudaGetSymbolAddress((void**)&wol, g_Wol);
    cudaGetSymbolAddress((void**)&aoh, g_AOh); cudaGetSymbolAddress((void**)&aol, g_AOl);
    cudaGetSymbolAddress((void**)&Qh, g_Qh);
    cudaGetSymbolAddress((void**)&Kh, g_Kh);
    cudaGetSymbolAddress((void**)&Vh, g_Vh);

    CvtArgs ca;
    ca.src[0] = query; ca.hi[0] = qh;  ca.lo[0] = ql;
    ca.src[1] = key;   ca.hi[1] = kh;  ca.lo[1] = kl;
    ca.src[2] = value; ca.hi[2] = vh;  ca.lo[2] = vl;
    ca.src[3] = Wq;    ca.hi[3] = wqh; ca.lo[3] = wql;
    ca.src[4] = Wk;    ca.hi[4] = wkh; ca.lo[4] = wkl;
    ca.src[5] = Wv;    ca.hi[5] = wvh; ca.lo[5] = wvl;
    ca.src[6] = Wo;    ca.hi[6] = woh; ca.lo[6] = wol;
    cvt_split_all<<<CVT_TOTAL_BLOCKS, 256>>>(ca);

    cudaFuncSetAttribute(gemm_bf16split2,
                         cudaFuncAttributeMaxDynamicSharedMemorySize, GSMEM_BYTES);
    dim3 ggrid(MROWS / 128, D_MODEL / 128);
    gemm_bf16split2<<<ggrid, 256, GSMEM_BYTES>>>(qh, ql, wqh, wql, bq, Qh, 1, 0.125f * LOG2E);
    gemm_bf16split2<<<ggrid, 256, GSMEM_BYTES>>>(kh, kl, wkh, wkl, bk, Kh, 1, 1.0f);
    gemm_bf16split2<<<ggrid, 256, GSMEM_BYTES>>>(vh, vl, wvh, wvl, bv, Vh, 1, 1.0f);

    dim3 fgrid(SEQ / 128, NHEADS, NBATCH);
    flash_attn_f16<<<fgrid, 256>>>(Qh, Kh, Vh, aoh, aol);

    gemm_bf16split2<<<ggrid, 256, GSMEM_BYTES>>>(aoh, aol, woh, wol, bo, out, 0, 1.0f);
}